// round 2
// baseline (speedup 1.0000x reference)
#include <cuda_runtime.h>
#include <math.h>

// ---------------------------------------------------------------------------
// Problem constants
// ---------------------------------------------------------------------------
#define LSEQ 512
#define BSZ  32
#define HID  256
#define LB   (LSEQ*BSZ)   // 16384 rows (row index = l*32 + b)
#define G3   768          // 3*H
#define H2   512          // 2*H
#define NF   512          // attention feature rows (384 fe + 128 v)
#define GRU_G 64          // blocks per direction in recurrence

// ---------------------------------------------------------------------------
// Scratch (device globals; no allocation allowed)
// ---------------------------------------------------------------------------
__device__ float d_x[LB * 256];            // embedded input (L,B,E)
__device__ float d_gi[2 * LB * G3];        // input-projection gates, reused l0/l1
__device__ float d_seq0[LB * H2];          // layer0 output (L,B,2H)
__device__ float d_seq1[LB * H2];          // layer1 output = rnn (L,B,2H)
__device__ float d_energy[LB * NF];        // energies -> probs (in place)
__device__ float d_Mb[NF * H2];            // fused attention matrix (F,2H)
__device__ float d_cb[NF];                 // fused attention bias
__device__ int   d_flags[2 * 2 * GRU_G];   // per-layer, per-dir, per-block step counters

// ---------------------------------------------------------------------------
// small helpers
// ---------------------------------------------------------------------------
__device__ __forceinline__ float fast_sig(float x) { return 1.0f / (1.0f + __expf(-x)); }
__device__ __forceinline__ float fast_tanh(float x) { return 2.0f / (1.0f + __expf(-2.0f * x)) - 1.0f; }

__global__ void zero_flags_kernel(int* flags) {
    int i = threadIdx.x;
    if (i < 2 * 2 * GRU_G) flags[i] = 0;
}

// x[(l*32+b)*256 + :] = emb[tok[b*512+l]]
__global__ void embed_kernel(const int* __restrict__ tok,
                             const float* __restrict__ emb,
                             float* __restrict__ X) {
    int r = blockIdx.x;                 // 0..16383
    int l = r >> 5, b = r & 31;
    int t = tok[b * LSEQ + l];
    const float4* src = (const float4*)(emb + (long)t * 256);
    float4* dst = (float4*)(X + (long)r * 256);
    dst[threadIdx.x] = src[threadIdx.x];   // 64 threads * float4
}

// Fold attention projections:
// f < 384: Mb[f,k] = sum_d fe[f,d]*fa_w[d,k];  cb[f] = sum_d fe[f,d]*fa_b[d]
// f >=384: Mb[f,k] = sum_d v[f-384,d]*la_w[d,k]; cb[f] = sum_d v[..]*la_b[d]
__global__ void build_M_kernel(const float* __restrict__ fe,
                               const float* __restrict__ vmat,
                               const float* __restrict__ fa_w,
                               const float* __restrict__ la_w,
                               const float* __restrict__ fa_b,
                               const float* __restrict__ la_b,
                               float* __restrict__ Mb, float* __restrict__ cb) {
    int f = blockIdx.x;                 // 0..511
    int tid = threadIdx.x;              // 128
    __shared__ float u[256];
    __shared__ float red[128];
    const float* U  = (f < 384) ? (fe + (long)f * 256) : (vmat + (long)(f - 384) * 256);
    const float* W  = (f < 384) ? fa_w : la_w;
    const float* Bv = (f < 384) ? fa_b : la_b;
    u[tid]       = U[tid];
    u[tid + 128] = U[tid + 128];
    float cpart = u[tid] * Bv[tid] + u[tid + 128] * Bv[tid + 128];
    __syncthreads();
    float a0 = 0.f, a1 = 0.f, a2 = 0.f, a3 = 0.f;
    #pragma unroll 4
    for (int d = 0; d < 256; d++) {
        float ud = u[d];
        float4 w = *(const float4*)(W + (long)d * H2 + tid * 4);
        a0 += ud * w.x; a1 += ud * w.y; a2 += ud * w.z; a3 += ud * w.w;
    }
    *(float4*)(Mb + (long)f * H2 + tid * 4) = make_float4(a0, a1, a2, a3);
    red[tid] = cpart; __syncthreads();
    for (int s = 64; s; s >>= 1) { if (tid < s) red[tid] += red[tid + s]; __syncthreads(); }
    if (tid == 0) cb[f] = red[0];
}

// ---------------------------------------------------------------------------
// C(M,N) = A(M,K) @ B(N,K)^T + bias(N).   128x128 tile, BK=8, 256 thr, 8x8 micro
// ---------------------------------------------------------------------------
__global__ __launch_bounds__(256) void gemm_nt_kernel(
    const float* __restrict__ A, const float* __restrict__ B,
    const float* __restrict__ bias, float* __restrict__ C,
    int M, int N, int K)
{
    __shared__ __align__(16) float As[8][128];
    __shared__ __align__(16) float Bs[8][128];
    const int m0 = blockIdx.x * 128, n0 = blockIdx.y * 128;
    const int tid = threadIdx.x;
    const int lr = tid >> 1, lc = (tid & 1) * 4;
    const int tx = tid & 15, ty = tid >> 4;
    const float* Ap = A + (long)(m0 + lr) * K + lc;
    const float* Bp = B + (long)(n0 + lr) * K + lc;
    float acc[8][8];
    #pragma unroll
    for (int i = 0; i < 8; i++)
        #pragma unroll
        for (int j = 0; j < 8; j++) acc[i][j] = 0.f;

    float4 av = *(const float4*)Ap;
    float4 bv = *(const float4*)Bp;
    for (int k0 = 0; k0 < K; k0 += 8) {
        __syncthreads();
        As[lc+0][lr]=av.x; As[lc+1][lr]=av.y; As[lc+2][lr]=av.z; As[lc+3][lr]=av.w;
        Bs[lc+0][lr]=bv.x; Bs[lc+1][lr]=bv.y; Bs[lc+2][lr]=bv.z; Bs[lc+3][lr]=bv.w;
        __syncthreads();
        if (k0 + 8 < K) {
            av = *(const float4*)(Ap + k0 + 8);
            bv = *(const float4*)(Bp + k0 + 8);
        }
        #pragma unroll
        for (int kk = 0; kk < 8; kk++) {
            float a[8], b[8];
            *(float4*)&a[0] = *(const float4*)&As[kk][ty*8];
            *(float4*)&a[4] = *(const float4*)&As[kk][ty*8+4];
            *(float4*)&b[0] = *(const float4*)&Bs[kk][tx*8];
            *(float4*)&b[4] = *(const float4*)&Bs[kk][tx*8+4];
            #pragma unroll
            for (int i = 0; i < 8; i++)
                #pragma unroll
                for (int j = 0; j < 8; j++)
                    acc[i][j] += a[i] * b[j];
        }
    }
    float bvr[8];
    #pragma unroll
    for (int j = 0; j < 8; j++) bvr[j] = bias[n0 + tx*8 + j];
    #pragma unroll
    for (int i = 0; i < 8; i++) {
        float* crow = C + (long)(m0 + ty*8 + i) * N + n0 + tx*8;
        float4 o;
        o.x=acc[i][0]+bvr[0]; o.y=acc[i][1]+bvr[1]; o.z=acc[i][2]+bvr[2]; o.w=acc[i][3]+bvr[3];
        *(float4*)crow = o;
        o.x=acc[i][4]+bvr[4]; o.y=acc[i][5]+bvr[5]; o.z=acc[i][6]+bvr[6]; o.w=acc[i][7]+bvr[7];
        *(float4*)(crow + 4) = o;
    }
}

// ---------------------------------------------------------------------------
// Context batched GEMM (TN): C[b](F=512,N=512) = sum_l P[l,f] * R[l,h]
// ---------------------------------------------------------------------------
__global__ __launch_bounds__(256) void gemm_tn_ctx_kernel(
    const float* __restrict__ P, const float* __restrict__ R,
    float* __restrict__ C)
{
    __shared__ __align__(16) float As[8][128];
    __shared__ __align__(16) float Bs[8][128];
    const int b  = blockIdx.z;
    const int m0 = blockIdx.x * 128, n0 = blockIdx.y * 128;
    const int tid = threadIdx.x;
    const int lrow = tid >> 5;            // 0..7
    const int c4   = (tid & 31) * 4;      // 0..124
    const int tx = tid & 15, ty = tid >> 4;
    float acc[8][8];
    #pragma unroll
    for (int i = 0; i < 8; i++)
        #pragma unroll
        for (int j = 0; j < 8; j++) acc[i][j] = 0.f;

    long base0 = ((long)lrow * 32 + b) * H2;
    float4 av = *(const float4*)(P + base0 + m0 + c4);
    float4 bv = *(const float4*)(R + base0 + n0 + c4);
    for (int l0 = 0; l0 < LSEQ; l0 += 8) {
        __syncthreads();
        *(float4*)&As[lrow][c4] = av;
        *(float4*)&Bs[lrow][c4] = bv;
        __syncthreads();
        if (l0 + 8 < LSEQ) {
            long base = ((long)(l0 + 8 + lrow) * 32 + b) * H2;
            av = *(const float4*)(P + base + m0 + c4);
            bv = *(const float4*)(R + base + n0 + c4);
        }
        #pragma unroll
        for (int kk = 0; kk < 8; kk++) {
            float a[8], bb[8];
            *(float4*)&a[0]  = *(const float4*)&As[kk][ty*8];
            *(float4*)&a[4]  = *(const float4*)&As[kk][ty*8+4];
            *(float4*)&bb[0] = *(const float4*)&Bs[kk][tx*8];
            *(float4*)&bb[4] = *(const float4*)&Bs[kk][tx*8+4];
            #pragma unroll
            for (int i = 0; i < 8; i++)
                #pragma unroll
                for (int j = 0; j < 8; j++)
                    acc[i][j] += a[i] * bb[j];
        }
    }
    #pragma unroll
    for (int i = 0; i < 8; i++) {
        float* crow = C + ((long)b * NF + m0 + ty*8 + i) * H2 + n0 + tx*8;
        float4 o;
        o.x=acc[i][0]; o.y=acc[i][1]; o.z=acc[i][2]; o.w=acc[i][3];
        *(float4*)crow = o;
        o.x=acc[i][4]; o.y=acc[i][5]; o.z=acc[i][6]; o.w=acc[i][7];
        *(float4*)(crow + 4) = o;
    }
}

// ---------------------------------------------------------------------------
// GRU recurrence v2. Persistent, per-block flag barrier (no atomics).
// Block (dir, g): owns hidden units c0 = g*4 .. +3 (12 gate rows in SMEM).
// 256 threads = 32 batches x 8 k-splits(32 each). FFMA register-blocked.
// Cross-SM h exchange via L2 (__ldcg), no reader-side fences.
// ---------------------------------------------------------------------------
__global__ __launch_bounds__(256) void gru_layer_kernel(
    const float* __restrict__ gi,    // (2, 16384, 768)  includes b_ih
    const float* __restrict__ whh,   // (2, 768, 256)
    const float* __restrict__ bhh,   // (2, 768)
    const float* __restrict__ h0,    // (2, 32, 256)
    float* __restrict__ out,         // (16384, 512), dir d writes cols d*256..
    int* __restrict__ flags)         // (2, 64)
{
    const int dir = blockIdx.x >> 6;
    const int g   = blockIdx.x & 63;
    const int c0  = g * 4;
    const int tid = threadIdx.x;
    const int b   = tid >> 3;          // 0..31  (batch)
    const int sub = tid & 7;           // 0..7   (k-split)
    const int kbase = sub * 32;

    __shared__ __align__(16) float w_s[12 * 288];   // [row][sub][36]  (pad 4)
    __shared__ float bhh_s[12];

    const float* whh_d = whh + (long)dir * G3 * HID;
    for (int i = tid; i < 12 * 256; i += 256) {
        int row = i >> 8, k = i & 255;
        int R = (row >> 2) * 256 + c0 + (row & 3);   // gate*256 + c0 + j
        w_s[row * 288 + (k >> 5) * 36 + (k & 31)] = whh_d[(long)R * HID + k];
    }
    if (tid < 12)
        bhh_s[tid] = bhh[dir * G3 + (tid >> 2) * 256 + c0 + (tid & 3)];
    __syncthreads();

    const float* gi_d = gi + (long)dir * LB * G3;
    volatile int* flg = (volatile int*)(flags + dir * GRU_G);
    const int srcsub = g >> 3;   // lane (within 8-group) holding h_prev[c0..c0+3]
    const int qh     = g & 7;    // float4 index within that lane's h[]

    for (int t = 0; t < LSEQ; t++) {
        int p  = dir ? (LSEQ - 1 - t) : t;
        int pp = dir ? (p + 1) : (p - 1);

        // prefetch gi for this step (independent of the barrier)
        float4 ga, gz, gn;
        if (sub == 0) {
            const float* grow = gi_d + ((long)p * BSZ + b) * G3;
            ga = __ldg((const float4*)(grow + c0));
            gz = __ldg((const float4*)(grow + 256 + c0));
            gn = __ldg((const float4*)(grow + 512 + c0));
        }

        // barrier: wait for all 64 blocks of this dir to finish step t-1
        if (t > 0) {
            if (tid < GRU_G) {
                while (flg[tid] < t) { }
            }
            __syncthreads();
        }

        // load h_prev slice (batch b, k = kbase..kbase+31) via L2
        float4 h[8];
        const float* hb = (t == 0)
            ? (h0 + ((long)dir * BSZ + b) * HID)
            : (out + ((long)pp * BSZ + b) * H2 + dir * HID);
        #pragma unroll
        for (int q = 0; q < 8; q++)
            h[q] = __ldcg((const float4*)(hb + kbase + q * 4));

        float acc[12];
        #pragma unroll
        for (int r = 0; r < 12; r++) acc[r] = 0.f;
        #pragma unroll
        for (int q = 0; q < 8; q++) {
            #pragma unroll
            for (int row = 0; row < 12; row++) {
                float4 w = *(const float4*)&w_s[row * 288 + sub * 36 + q * 4];
                acc[row] += h[q].x*w.x + h[q].y*w.y + h[q].z*w.z + h[q].w*w.w;
            }
        }

        // hp = h_prev[b, c0..c0+3] via intra-group shuffle (no extra load)
        float hp0 = __shfl_sync(0xffffffffu, h[qh].x, srcsub, 8);
        float hp1 = __shfl_sync(0xffffffffu, h[qh].y, srcsub, 8);
        float hp2 = __shfl_sync(0xffffffffu, h[qh].z, srcsub, 8);
        float hp3 = __shfl_sync(0xffffffffu, h[qh].w, srcsub, 8);

        // reduce over the 8 k-split lanes
        #pragma unroll
        for (int off = 4; off; off >>= 1)
            #pragma unroll
            for (int r = 0; r < 12; r++)
                acc[r] += __shfl_down_sync(0xffffffffu, acc[r], off, 8);

        if (sub == 0) {
            float hp[4] = {hp0, hp1, hp2, hp3};
            float gav[4], gzv[4], gnv[4], hn[4];
            *(float4*)gav = ga; *(float4*)gzv = gz; *(float4*)gnv = gn;
            #pragma unroll
            for (int j = 0; j < 4; j++) {
                float r = fast_sig(gav[j] + bhh_s[j]     + acc[j]);
                float z = fast_sig(gzv[j] + bhh_s[4 + j] + acc[4 + j]);
                float n = fast_tanh(gnv[j] + r * (acc[8 + j] + bhh_s[8 + j]));
                hn[j] = (1.f - z) * n + z * hp[j];
            }
            *(float4*)(out + ((long)p * BSZ + b) * H2 + dir * HID + c0) =
                make_float4(hn[0], hn[1], hn[2], hn[3]);
        }
        __threadfence();       // drain h stores to L2 before flag publish
        __syncthreads();       // all warps' stores fenced
        if (tid == 0) flg[g] = t + 1;
    }
}

// ---------------------------------------------------------------------------
// Row softmax over 512 features, in place (energies -> probs)
// ---------------------------------------------------------------------------
__global__ void softmax_kernel(float* __restrict__ E) {
    int row = blockIdx.x, tid = threadIdx.x;   // 128 threads
    float* Er = E + (long)row * NF;
    float4 v = ((float4*)Er)[tid];
    __shared__ float sred[8];
    float m = fmaxf(fmaxf(v.x, v.y), fmaxf(v.z, v.w));
    #pragma unroll
    for (int off = 16; off; off >>= 1) m = fmaxf(m, __shfl_xor_sync(0xffffffffu, m, off));
    if ((tid & 31) == 0) sred[tid >> 5] = m;
    __syncthreads();
    m = fmaxf(fmaxf(sred[0], sred[1]), fmaxf(sred[2], sred[3]));
    float e0 = expf(v.x - m), e1 = expf(v.y - m), e2 = expf(v.z - m), e3 = expf(v.w - m);
    float s = e0 + e1 + e2 + e3;
    #pragma unroll
    for (int off = 16; off; off >>= 1) s += __shfl_xor_sync(0xffffffffu, s, off);
    __syncthreads();
    if ((tid & 31) == 0) sred[4 + (tid >> 5)] = s;
    __syncthreads();
    s = sred[4] + sred[5] + sred[6] + sred[7];
    float inv = 1.f / s;
    ((float4*)Er)[tid] = make_float4(e0 * inv, e1 * inv, e2 * inv, e3 * inv);
}

// attn_out[b][f][l] = probs[(l*32+b)*512 + f]   (tiled transpose)
__global__ void transpose_kernel(const float* __restrict__ P, float* __restrict__ outp) {
    __shared__ float t[32][33];
    int b = blockIdx.z;
    int f0 = blockIdx.x * 32, l0 = blockIdx.y * 32;
    int tx = threadIdx.x, ty = threadIdx.y;   // (32,8)
    #pragma unroll
    for (int i = 0; i < 32; i += 8)
        t[ty + i][tx] = P[((long)(l0 + ty + i) * BSZ + b) * NF + f0 + tx];
    __syncthreads();
    #pragma unroll
    for (int i = 0; i < 32; i += 8)
        outp[((long)b * NF + f0 + ty + i) * LSEQ + l0 + tx] = t[tx][ty + i];
}

// ---------------------------------------------------------------------------
// Launch
// ---------------------------------------------------------------------------
template <typename T>
static T* symaddr(const void* sym) {
    void* p = nullptr;
    cudaGetSymbolAddress(&p, sym);
    return (T*)p;
}

extern "C" void kernel_launch(void* const* d_in, const int* in_sizes, int n_in,
                              void* d_out, int out_size) {
    const int*   tok    = (const int*)d_in[0];
    const float* hidden = (const float*)d_in[2];
    const float* fe     = (const float*)d_in[3];
    const float* emb    = (const float*)d_in[4];
    const float* w_ih0  = (const float*)d_in[5];
    const float* w_hh0  = (const float*)d_in[6];
    const float* b_ih0  = (const float*)d_in[7];
    const float* b_hh0  = (const float*)d_in[8];
    const float* w_ih1  = (const float*)d_in[9];
    const float* w_hh1  = (const float*)d_in[10];
    const float* b_ih1  = (const float*)d_in[11];
    const float* b_hh1  = (const float*)d_in[12];
    const float* la_w   = (const float*)d_in[13];
    const float* la_b   = (const float*)d_in[14];
    const float* fa_w   = (const float*)d_in[15];
    const float* fa_b   = (const float*)d_in[16];
    const float* vmat   = (const float*)d_in[17];

    float* ctx_out  = (float*)d_out;                       // (32,512,512)
    float* attn_out = ctx_out + (size_t)BSZ * NF * LSEQ;   // (32,512,512)

    float* x   = symaddr<float>(d_x);
    float* gi  = symaddr<float>(d_gi);
    float* s0  = symaddr<float>(d_seq0);
    float* s1  = symaddr<float>(d_seq1);
    float* en  = symaddr<float>(d_energy);
    float* Mb  = symaddr<float>(d_Mb);
    float* cb  = symaddr<float>(d_cb);
    int*   flg = symaddr<int>(d_flags);

    zero_flags_kernel<<<1, 256>>>(flg);
    embed_kernel<<<LB, 64>>>(tok, emb, x);
    build_M_kernel<<<NF, 128>>>(fe, vmat, fa_w, la_w, fa_b, la_b, Mb, cb);

    dim3 gGi(LB / 128, G3 / 128);   // (128, 6)
    gemm_nt_kernel<<<gGi, 256>>>(x, w_ih0,            b_ih0,       gi,                16384, 768, 256);
    gemm_nt_kernel<<<gGi, 256>>>(x, w_ih0 + 768*256,  b_ih0 + 768, gi + (long)LB*G3,  16384, 768, 256);

    gru_layer_kernel<<<128, 256>>>(gi, w_hh0, b_hh0, hidden, s0, flg);

    gemm_nt_kernel<<<gGi, 256>>>(s0, w_ih1,           b_ih1,       gi,                16384, 768, 512);
    gemm_nt_kernel<<<gGi, 256>>>(s0, w_ih1 + 768*512, b_ih1 + 768, gi + (long)LB*G3,  16384, 768, 512);

    gru_layer_kernel<<<128, 256>>>(gi, w_hh1, b_hh1, hidden + 2*BSZ*HID, s1, flg + 2*GRU_G);

    dim3 gEn(LB / 128, NF / 128);   // (128, 4)
    gemm_nt_kernel<<<gEn, 256>>>(s1, Mb, cb, en, 16384, 512, 512);

    softmax_kernel<<<LB, 128>>>(en);

    dim3 gT(NF / 32, LSEQ / 32, BSZ);
    transpose_kernel<<<gT, dim3(32, 8)>>>(en, attn_out);

    dim3 gC(NF / 128, H2 / 128, BSZ);   // (4,4,32)
    gemm_tn_ctx_kernel<<<gC, 256>>>(en, s1, ctx_out);
}

// round 3
// speedup vs baseline: 1.0117x; 1.0117x over previous
#include <cuda_runtime.h>
#include <math.h>

// ---------------------------------------------------------------------------
// Problem constants
// ---------------------------------------------------------------------------
#define LSEQ 512
#define BSZ  32
#define HID  256
#define LB   (LSEQ*BSZ)   // 16384 rows (row index = l*32 + b)
#define G3   768          // 3*H
#define H2   512          // 2*H
#define NF   512          // attention feature rows (384 fe + 128 v)
#define GRU_G 64          // blocks per direction in recurrence

// ---------------------------------------------------------------------------
// Scratch (device globals; no allocation allowed)
// ---------------------------------------------------------------------------
__device__ float d_x[LB * 256];            // embedded input (L,B,E)
__device__ float d_gi[2 * LB * G3];        // input-projection gates, reused l0/l1
__device__ float d_seq0[LB * H2];          // layer0 output (L,B,2H)
__device__ float d_seq1[LB * H2];          // layer1 output = rnn (L,B,2H)
__device__ float d_energy[LB * NF];        // energies -> probs (in place)
__device__ float d_Mb[NF * H2];            // fused attention matrix (F,2H)
__device__ float d_cb[NF];                 // fused attention bias
__device__ int   d_flags[2 * 2 * GRU_G];   // per-layer, per-dir, per-block step counters

// ---------------------------------------------------------------------------
// small helpers
// ---------------------------------------------------------------------------
__device__ __forceinline__ float fast_sig(float x) { return 1.0f / (1.0f + __expf(-x)); }
__device__ __forceinline__ float fast_tanh(float x) { return 2.0f / (1.0f + __expf(-2.0f * x)) - 1.0f; }

__global__ void zero_flags_kernel(int* flags) {
    int i = threadIdx.x;
    if (i < 2 * 2 * GRU_G) flags[i] = 0;
}

// x[(l*32+b)*256 + :] = emb[tok[b*512+l]]
__global__ void embed_kernel(const int* __restrict__ tok,
                             const float* __restrict__ emb,
                             float* __restrict__ X) {
    int r = blockIdx.x;                 // 0..16383
    int l = r >> 5, b = r & 31;
    int t = tok[b * LSEQ + l];
    const float4* src = (const float4*)(emb + (long)t * 256);
    float4* dst = (float4*)(X + (long)r * 256);
    dst[threadIdx.x] = src[threadIdx.x];   // 64 threads * float4
}

// Fold attention projections:
// f < 384: Mb[f,k] = sum_d fe[f,d]*fa_w[d,k];  cb[f] = sum_d fe[f,d]*fa_b[d]
// f >=384: Mb[f,k] = sum_d v[f-384,d]*la_w[d,k]; cb[f] = sum_d v[..]*la_b[d]
__global__ void build_M_kernel(const float* __restrict__ fe,
                               const float* __restrict__ vmat,
                               const float* __restrict__ fa_w,
                               const float* __restrict__ la_w,
                               const float* __restrict__ fa_b,
                               const float* __restrict__ la_b,
                               float* __restrict__ Mb, float* __restrict__ cb) {
    int f = blockIdx.x;                 // 0..511
    int tid = threadIdx.x;              // 128
    __shared__ float u[256];
    __shared__ float red[128];
    const float* U  = (f < 384) ? (fe + (long)f * 256) : (vmat + (long)(f - 384) * 256);
    const float* W  = (f < 384) ? fa_w : la_w;
    const float* Bv = (f < 384) ? fa_b : la_b;
    u[tid]       = U[tid];
    u[tid + 128] = U[tid + 128];
    float cpart = u[tid] * Bv[tid] + u[tid + 128] * Bv[tid + 128];
    __syncthreads();
    float a0 = 0.f, a1 = 0.f, a2 = 0.f, a3 = 0.f;
    #pragma unroll 4
    for (int d = 0; d < 256; d++) {
        float ud = u[d];
        float4 w = *(const float4*)(W + (long)d * H2 + tid * 4);
        a0 += ud * w.x; a1 += ud * w.y; a2 += ud * w.z; a3 += ud * w.w;
    }
    *(float4*)(Mb + (long)f * H2 + tid * 4) = make_float4(a0, a1, a2, a3);
    red[tid] = cpart; __syncthreads();
    for (int s = 64; s; s >>= 1) { if (tid < s) red[tid] += red[tid + s]; __syncthreads(); }
    if (tid == 0) cb[f] = red[0];
}

// ---------------------------------------------------------------------------
// C(M,N) = A(M,K) @ B(N,K)^T + bias(N).   128x128 tile, BK=8, 256 thr, 8x8 micro
// ---------------------------------------------------------------------------
__global__ __launch_bounds__(256) void gemm_nt_kernel(
    const float* __restrict__ A, const float* __restrict__ B,
    const float* __restrict__ bias, float* __restrict__ C,
    int M, int N, int K)
{
    __shared__ __align__(16) float As[8][128];
    __shared__ __align__(16) float Bs[8][128];
    const int m0 = blockIdx.x * 128, n0 = blockIdx.y * 128;
    const int tid = threadIdx.x;
    const int lr = tid >> 1, lc = (tid & 1) * 4;
    const int tx = tid & 15, ty = tid >> 4;
    const float* Ap = A + (long)(m0 + lr) * K + lc;
    const float* Bp = B + (long)(n0 + lr) * K + lc;
    float acc[8][8];
    #pragma unroll
    for (int i = 0; i < 8; i++)
        #pragma unroll
        for (int j = 0; j < 8; j++) acc[i][j] = 0.f;

    float4 av = *(const float4*)Ap;
    float4 bv = *(const float4*)Bp;
    for (int k0 = 0; k0 < K; k0 += 8) {
        __syncthreads();
        As[lc+0][lr]=av.x; As[lc+1][lr]=av.y; As[lc+2][lr]=av.z; As[lc+3][lr]=av.w;
        Bs[lc+0][lr]=bv.x; Bs[lc+1][lr]=bv.y; Bs[lc+2][lr]=bv.z; Bs[lc+3][lr]=bv.w;
        __syncthreads();
        if (k0 + 8 < K) {
            av = *(const float4*)(Ap + k0 + 8);
            bv = *(const float4*)(Bp + k0 + 8);
        }
        #pragma unroll
        for (int kk = 0; kk < 8; kk++) {
            float a[8], b[8];
            *(float4*)&a[0] = *(const float4*)&As[kk][ty*8];
            *(float4*)&a[4] = *(const float4*)&As[kk][ty*8+4];
            *(float4*)&b[0] = *(const float4*)&Bs[kk][tx*8];
            *(float4*)&b[4] = *(const float4*)&Bs[kk][tx*8+4];
            #pragma unroll
            for (int i = 0; i < 8; i++)
                #pragma unroll
                for (int j = 0; j < 8; j++)
                    acc[i][j] += a[i] * b[j];
        }
    }
    float bvr[8];
    #pragma unroll
    for (int j = 0; j < 8; j++) bvr[j] = bias[n0 + tx*8 + j];
    #pragma unroll
    for (int i = 0; i < 8; i++) {
        float* crow = C + (long)(m0 + ty*8 + i) * N + n0 + tx*8;
        float4 o;
        o.x=acc[i][0]+bvr[0]; o.y=acc[i][1]+bvr[1]; o.z=acc[i][2]+bvr[2]; o.w=acc[i][3]+bvr[3];
        *(float4*)crow = o;
        o.x=acc[i][4]+bvr[4]; o.y=acc[i][5]+bvr[5]; o.z=acc[i][6]+bvr[6]; o.w=acc[i][7]+bvr[7];
        *(float4*)(crow + 4) = o;
    }
}

// ---------------------------------------------------------------------------
// Context batched GEMM (TN): C[b](F=512,N=512) = sum_l P[l,f] * R[l,h]
// ---------------------------------------------------------------------------
__global__ __launch_bounds__(256) void gemm_tn_ctx_kernel(
    const float* __restrict__ P, const float* __restrict__ R,
    float* __restrict__ C)
{
    __shared__ __align__(16) float As[8][128];
    __shared__ __align__(16) float Bs[8][128];
    const int b  = blockIdx.z;
    const int m0 = blockIdx.x * 128, n0 = blockIdx.y * 128;
    const int tid = threadIdx.x;
    const int lrow = tid >> 5;            // 0..7
    const int c4   = (tid & 31) * 4;      // 0..124
    const int tx = tid & 15, ty = tid >> 4;
    float acc[8][8];
    #pragma unroll
    for (int i = 0; i < 8; i++)
        #pragma unroll
        for (int j = 0; j < 8; j++) acc[i][j] = 0.f;

    long base0 = ((long)lrow * 32 + b) * H2;
    float4 av = *(const float4*)(P + base0 + m0 + c4);
    float4 bv = *(const float4*)(R + base0 + n0 + c4);
    for (int l0 = 0; l0 < LSEQ; l0 += 8) {
        __syncthreads();
        *(float4*)&As[lrow][c4] = av;
        *(float4*)&Bs[lrow][c4] = bv;
        __syncthreads();
        if (l0 + 8 < LSEQ) {
            long base = ((long)(l0 + 8 + lrow) * 32 + b) * H2;
            av = *(const float4*)(P + base + m0 + c4);
            bv = *(const float4*)(R + base + n0 + c4);
        }
        #pragma unroll
        for (int kk = 0; kk < 8; kk++) {
            float a[8], bb[8];
            *(float4*)&a[0]  = *(const float4*)&As[kk][ty*8];
            *(float4*)&a[4]  = *(const float4*)&As[kk][ty*8+4];
            *(float4*)&bb[0] = *(const float4*)&Bs[kk][tx*8];
            *(float4*)&bb[4] = *(const float4*)&Bs[kk][tx*8+4];
            #pragma unroll
            for (int i = 0; i < 8; i++)
                #pragma unroll
                for (int j = 0; j < 8; j++)
                    acc[i][j] += a[i] * bb[j];
        }
    }
    #pragma unroll
    for (int i = 0; i < 8; i++) {
        float* crow = C + ((long)b * NF + m0 + ty*8 + i) * H2 + n0 + tx*8;
        float4 o;
        o.x=acc[i][0]; o.y=acc[i][1]; o.z=acc[i][2]; o.w=acc[i][3];
        *(float4*)crow = o;
        o.x=acc[i][4]; o.y=acc[i][5]; o.z=acc[i][6]; o.w=acc[i][7];
        *(float4*)(crow + 4) = o;
    }
}

// ---------------------------------------------------------------------------
// GRU recurrence v3. Persistent, per-block flag barrier, minimal fencing:
//   writers: __stcg h -> L2, __syncthreads, tid0: __threadfence + flag store
//   readers: 64 threads poll 64 flags (volatile), then __ldcg h from L2
// Block (dir, g): owns hidden units c0 = g*4 .. +3 (12 gate rows in SMEM).
// 256 threads = 32 batches x 8 k-splits(32 each). FFMA register-blocked.
// ---------------------------------------------------------------------------
__global__ __launch_bounds__(256) void gru_layer_kernel(
    const float* __restrict__ gi,    // (2, 16384, 768)  includes b_ih
    const float* __restrict__ whh,   // (2, 768, 256)
    const float* __restrict__ bhh,   // (2, 768)
    const float* __restrict__ h0,    // (2, 32, 256)
    float* __restrict__ out,         // (16384, 512), dir d writes cols d*256..
    int* __restrict__ flags)         // (2, 64)
{
    const int dir = blockIdx.x >> 6;
    const int g   = blockIdx.x & 63;
    const int c0  = g * 4;
    const int tid = threadIdx.x;
    const int b   = tid >> 3;          // 0..31  (batch)
    const int sub = tid & 7;           // 0..7   (k-split)
    const int kbase = sub * 32;

    __shared__ __align__(16) float w_s[12 * 288];   // [row][sub][36]  (pad 4)
    __shared__ float bhh_s[12];

    const float* whh_d = whh + (long)dir * G3 * HID;
    for (int i = tid; i < 12 * 256; i += 256) {
        int row = i >> 8, k = i & 255;
        int R = (row >> 2) * 256 + c0 + (row & 3);   // gate*256 + c0 + j
        w_s[row * 288 + (k >> 5) * 36 + (k & 31)] = whh_d[(long)R * HID + k];
    }
    if (tid < 12)
        bhh_s[tid] = bhh[dir * G3 + (tid >> 2) * 256 + c0 + (tid & 3)];
    __syncthreads();

    const float* gi_d = gi + (long)dir * LB * G3;
    volatile int* flg = (volatile int*)(flags + dir * GRU_G);
    const int srcsub = g >> 3;   // lane (within 8-group) holding h_prev[c0..c0+3]
    const int qh     = g & 7;    // float4 index within that lane's h[]

    for (int t = 0; t < LSEQ; t++) {
        int p  = dir ? (LSEQ - 1 - t) : t;
        int pp = dir ? (p + 1) : (p - 1);

        // prefetch gi for this step (independent of the barrier)
        float4 ga, gz, gn;
        if (sub == 0) {
            const float* grow = gi_d + ((long)p * BSZ + b) * G3;
            ga = __ldg((const float4*)(grow + c0));
            gz = __ldg((const float4*)(grow + 256 + c0));
            gn = __ldg((const float4*)(grow + 512 + c0));
        }

        // barrier: wait for all 64 blocks of this dir to finish step t-1
        if (t > 0) {
            if (tid < GRU_G) {
                while (flg[tid] < t) { }
            }
            __syncthreads();
        }

        // load h_prev slice (batch b, k = kbase..kbase+31) from L2
        float4 h[8];
        const float* hb = (t == 0)
            ? (h0 + ((long)dir * BSZ + b) * HID)
            : (out + ((long)pp * BSZ + b) * H2 + dir * HID);
        #pragma unroll
        for (int q = 0; q < 8; q++)
            h[q] = __ldcg((const float4*)(hb + kbase + q * 4));

        float acc[12];
        #pragma unroll
        for (int r = 0; r < 12; r++) acc[r] = 0.f;
        #pragma unroll
        for (int q = 0; q < 8; q++) {
            #pragma unroll
            for (int row = 0; row < 12; row++) {
                float4 w = *(const float4*)&w_s[row * 288 + sub * 36 + q * 4];
                acc[row] += h[q].x*w.x + h[q].y*w.y + h[q].z*w.z + h[q].w*w.w;
            }
        }

        // hp = h_prev[b, c0..c0+3] via intra-group shuffle (no extra load)
        float hp0 = __shfl_sync(0xffffffffu, h[qh].x, srcsub, 8);
        float hp1 = __shfl_sync(0xffffffffu, h[qh].y, srcsub, 8);
        float hp2 = __shfl_sync(0xffffffffu, h[qh].z, srcsub, 8);
        float hp3 = __shfl_sync(0xffffffffu, h[qh].w, srcsub, 8);

        // reduce over the 8 k-split lanes
        #pragma unroll
        for (int off = 4; off; off >>= 1)
            #pragma unroll
            for (int r = 0; r < 12; r++)
                acc[r] += __shfl_down_sync(0xffffffffu, acc[r], off, 8);

        if (sub == 0) {
            float hp[4] = {hp0, hp1, hp2, hp3};
            float gav[4], gzv[4], gnv[4], hn[4];
            *(float4*)gav = ga; *(float4*)gzv = gz; *(float4*)gnv = gn;
            #pragma unroll
            for (int j = 0; j < 4; j++) {
                float r = fast_sig(gav[j] + bhh_s[j]     + acc[j]);
                float z = fast_sig(gzv[j] + bhh_s[4 + j] + acc[4 + j]);
                float n = fast_tanh(gnv[j] + r * (acc[8 + j] + bhh_s[8 + j]));
                hn[j] = (1.f - z) * n + z * hp[j];
            }
            // straight to L2 (coherence point) so the fence below is cheap
            __stcg((float4*)(out + ((long)p * BSZ + b) * H2 + dir * HID + c0),
                   make_float4(hn[0], hn[1], hn[2], hn[3]));
        }
        __syncthreads();                 // all writers' stcg issued
        if (tid == 0) {
            __threadfence();             // single-thread gpu-scope fence
            flg[g] = t + 1;              // publish (volatile -> bypasses L1)
        }
    }
}

// ---------------------------------------------------------------------------
// Row softmax over 512 features, in place (energies -> probs)
// ---------------------------------------------------------------------------
__global__ void softmax_kernel(float* __restrict__ E) {
    int row = blockIdx.x, tid = threadIdx.x;   // 128 threads
    float* Er = E + (long)row * NF;
    float4 v = ((float4*)Er)[tid];
    __shared__ float sred[8];
    float m = fmaxf(fmaxf(v.x, v.y), fmaxf(v.z, v.w));
    #pragma unroll
    for (int off = 16; off; off >>= 1) m = fmaxf(m, __shfl_xor_sync(0xffffffffu, m, off));
    if ((tid & 31) == 0) sred[tid >> 5] = m;
    __syncthreads();
    m = fmaxf(fmaxf(sred[0], sred[1]), fmaxf(sred[2], sred[3]));
    float e0 = expf(v.x - m), e1 = expf(v.y - m), e2 = expf(v.z - m), e3 = expf(v.w - m);
    float s = e0 + e1 + e2 + e3;
    #pragma unroll
    for (int off = 16; off; off >>= 1) s += __shfl_xor_sync(0xffffffffu, s, off);
    __syncthreads();
    if ((tid & 31) == 0) sred[4 + (tid >> 5)] = s;
    __syncthreads();
    s = sred[4] + sred[5] + sred[6] + sred[7];
    float inv = 1.f / s;
    ((float4*)Er)[tid] = make_float4(e0 * inv, e1 * inv, e2 * inv, e3 * inv);
}

// attn_out[b][f][l] = probs[(l*32+b)*512 + f]   (tiled transpose)
__global__ void transpose_kernel(const float* __restrict__ P, float* __restrict__ outp) {
    __shared__ float t[32][33];
    int b = blockIdx.z;
    int f0 = blockIdx.x * 32, l0 = blockIdx.y * 32;
    int tx = threadIdx.x, ty = threadIdx.y;   // (32,8)
    #pragma unroll
    for (int i = 0; i < 32; i += 8)
        t[ty + i][tx] = P[((long)(l0 + ty + i) * BSZ + b) * NF + f0 + tx];
    __syncthreads();
    #pragma unroll
    for (int i = 0; i < 32; i += 8)
        outp[((long)b * NF + f0 + ty + i) * LSEQ + l0 + tx] = t[tx][ty + i];
}

// ---------------------------------------------------------------------------
// Launch
// ---------------------------------------------------------------------------
template <typename T>
static T* symaddr(const void* sym) {
    void* p = nullptr;
    cudaGetSymbolAddress(&p, sym);
    return (T*)p;
}

extern "C" void kernel_launch(void* const* d_in, const int* in_sizes, int n_in,
                              void* d_out, int out_size) {
    const int*   tok    = (const int*)d_in[0];
    const float* hidden = (const float*)d_in[2];
    const float* fe     = (const float*)d_in[3];
    const float* emb    = (const float*)d_in[4];
    const float* w_ih0  = (const float*)d_in[5];
    const float* w_hh0  = (const float*)d_in[6];
    const float* b_ih0  = (const float*)d_in[7];
    const float* b_hh0  = (const float*)d_in[8];
    const float* w_ih1  = (const float*)d_in[9];
    const float* w_hh1  = (const float*)d_in[10];
    const float* b_ih1  = (const float*)d_in[11];
    const float* b_hh1  = (const float*)d_in[12];
    const float* la_w   = (const float*)d_in[13];
    const float* la_b   = (const float*)d_in[14];
    const float* fa_w   = (const float*)d_in[15];
    const float* fa_b   = (const float*)d_in[16];
    const float* vmat   = (const float*)d_in[17];

    float* ctx_out  = (float*)d_out;                       // (32,512,512)
    float* attn_out = ctx_out + (size_t)BSZ * NF * LSEQ;   // (32,512,512)

    float* x   = symaddr<float>(d_x);
    float* gi  = symaddr<float>(d_gi);
    float* s0  = symaddr<float>(d_seq0);
    float* s1  = symaddr<float>(d_seq1);
    float* en  = symaddr<float>(d_energy);
    float* Mb  = symaddr<float>(d_Mb);
    float* cb  = symaddr<float>(d_cb);
    int*   flg = symaddr<int>(d_flags);

    zero_flags_kernel<<<1, 256>>>(flg);
    embed_kernel<<<LB, 64>>>(tok, emb, x);
    build_M_kernel<<<NF, 128>>>(fe, vmat, fa_w, la_w, fa_b, la_b, Mb, cb);

    dim3 gGi(LB / 128, G3 / 128);   // (128, 6)
    gemm_nt_kernel<<<gGi, 256>>>(x, w_ih0,            b_ih0,       gi,                16384, 768, 256);
    gemm_nt_kernel<<<gGi, 256>>>(x, w_ih0 + 768*256,  b_ih0 + 768, gi + (long)LB*G3,  16384, 768, 256);

    gru_layer_kernel<<<128, 256>>>(gi, w_hh0, b_hh0, hidden, s0, flg);

    gemm_nt_kernel<<<gGi, 256>>>(s0, w_ih1,           b_ih1,       gi,                16384, 768, 512);
    gemm_nt_kernel<<<gGi, 256>>>(s0, w_ih1 + 768*512, b_ih1 + 768, gi + (long)LB*G3,  16384, 768, 512);

    gru_layer_kernel<<<128, 256>>>(gi, w_hh1, b_hh1, hidden + 2*BSZ*HID, s1, flg + 2*GRU_G);

    dim3 gEn(LB / 128, NF / 128);   // (128, 4)
    gemm_nt_kernel<<<gEn, 256>>>(s1, Mb, cb, en, 16384, 512, 512);

    softmax_kernel<<<LB, 128>>>(en);

    dim3 gT(NF / 32, LSEQ / 32, BSZ);
    transpose_kernel<<<gT, dim3(32, 8)>>>(en, attn_out);

    dim3 gC(NF / 128, H2 / 128, BSZ);   // (4,4,32)
    gemm_tn_ctx_kernel<<<gC, 256>>>(en, s1, ctx_out);
}

// round 4
// speedup vs baseline: 1.3156x; 1.3004x over previous
#include <cuda_runtime.h>
#include <math.h>

// ---------------------------------------------------------------------------
// Problem constants
// ---------------------------------------------------------------------------
#define LSEQ 512
#define BSZ  32
#define HID  256
#define LB   (LSEQ*BSZ)   // 16384 rows (row index = l*32 + b)
#define G3   768          // 3*H
#define H2   512          // 2*H
#define NF   512          // attention feature rows (384 fe + 128 v)
#define GRU_G 64          // blocks per direction in recurrence
#define CNT_STRIDE 64     // ints between per-step counters (256B -> slice rotation)

// ---------------------------------------------------------------------------
// Scratch (device globals; no allocation allowed)
// ---------------------------------------------------------------------------
__device__ float d_x[LB * 256];            // embedded input (L,B,E)
__device__ float d_gi[2 * LB * G3];        // input-projection gates, reused l0/l1
__device__ float d_seq0[LB * H2];          // layer0 output (L,B,2H)
__device__ float d_seq1[LB * H2];          // layer1 output = rnn (L,B,2H)
__device__ float d_energy[LB * NF];        // energies -> probs (in place)
__device__ float d_Mb[NF * H2];            // fused attention matrix (F,2H)
__device__ float d_cb[NF];                 // fused attention bias
__device__ int   d_flags[2 * 2 * LSEQ * CNT_STRIDE];  // per-layer/dir/step counters

// ---------------------------------------------------------------------------
// helpers
// ---------------------------------------------------------------------------
__device__ __forceinline__ float fast_sig(float x) { return 1.0f / (1.0f + __expf(-x)); }
__device__ __forceinline__ float fast_tanh(float x) { return 2.0f / (1.0f + __expf(-2.0f * x)) - 1.0f; }

union F4U { float4 f; float fa[4]; unsigned long long u[2]; };

__device__ __forceinline__ void fma_x2(unsigned long long& d,
                                       unsigned long long a,
                                       unsigned long long b) {
    asm("fma.rn.f32x2 %0, %1, %2, %0;" : "+l"(d) : "l"(a), "l"(b));
}
__device__ __forceinline__ unsigned long long dup_x2(float v) {
    unsigned long long r; unsigned u = __float_as_uint(v);
    asm("mov.b64 %0, {%1, %1};" : "=l"(r) : "r"(u));
    return r;
}
__device__ __forceinline__ void unpack_x2(unsigned long long p, float& lo, float& hi) {
    unsigned a, b;
    asm("mov.b64 {%0, %1}, %2;" : "=r"(a), "=r"(b) : "l"(p));
    lo = __uint_as_float(a); hi = __uint_as_float(b);
}

__global__ void zero_flags_kernel(int* flags) {
    int i = blockIdx.x * 256 + threadIdx.x;
    if (i < 2 * 2 * LSEQ * CNT_STRIDE) flags[i] = 0;
}

// x[(l*32+b)*256 + :] = emb[tok[b*512+l]]
__global__ void embed_kernel(const int* __restrict__ tok,
                             const float* __restrict__ emb,
                             float* __restrict__ X) {
    int r = blockIdx.x;                 // 0..16383
    int l = r >> 5, b = r & 31;
    int t = tok[b * LSEQ + l];
    const float4* src = (const float4*)(emb + (long)t * 256);
    float4* dst = (float4*)(X + (long)r * 256);
    dst[threadIdx.x] = src[threadIdx.x];   // 64 threads * float4
}

// Fold attention projections into Mb (F,2H) and cb (F)
__global__ void build_M_kernel(const float* __restrict__ fe,
                               const float* __restrict__ vmat,
                               const float* __restrict__ fa_w,
                               const float* __restrict__ la_w,
                               const float* __restrict__ fa_b,
                               const float* __restrict__ la_b,
                               float* __restrict__ Mb, float* __restrict__ cb) {
    int f = blockIdx.x;                 // 0..511
    int tid = threadIdx.x;              // 128
    __shared__ float u[256];
    __shared__ float red[128];
    const float* U  = (f < 384) ? (fe + (long)f * 256) : (vmat + (long)(f - 384) * 256);
    const float* W  = (f < 384) ? fa_w : la_w;
    const float* Bv = (f < 384) ? fa_b : la_b;
    u[tid]       = U[tid];
    u[tid + 128] = U[tid + 128];
    float cpart = u[tid] * Bv[tid] + u[tid + 128] * Bv[tid + 128];
    __syncthreads();
    float a0 = 0.f, a1 = 0.f, a2 = 0.f, a3 = 0.f;
    #pragma unroll 4
    for (int d = 0; d < 256; d++) {
        float ud = u[d];
        float4 w = *(const float4*)(W + (long)d * H2 + tid * 4);
        a0 += ud * w.x; a1 += ud * w.y; a2 += ud * w.z; a3 += ud * w.w;
    }
    *(float4*)(Mb + (long)f * H2 + tid * 4) = make_float4(a0, a1, a2, a3);
    red[tid] = cpart; __syncthreads();
    for (int s = 64; s; s >>= 1) { if (tid < s) red[tid] += red[tid + s]; __syncthreads(); }
    if (tid == 0) cb[f] = red[0];
}

// ---------------------------------------------------------------------------
// C(M,N) = A(M,K) @ B(N,K)^T + bias(N).   128x128 tile, BK=8, 256 thr,
// 8x8 micro-tile via packed fma.rn.f32x2 (acc pairs along N).
// ---------------------------------------------------------------------------
__global__ __launch_bounds__(256) void gemm_nt_kernel(
    const float* __restrict__ A, const float* __restrict__ B,
    const float* __restrict__ bias, float* __restrict__ C,
    int M, int N, int K)
{
    __shared__ __align__(16) float As[8][128];
    __shared__ __align__(16) float Bs[8][128];
    const int m0 = blockIdx.x * 128, n0 = blockIdx.y * 128;
    const int tid = threadIdx.x;
    const int lr = tid >> 1, lc = (tid & 1) * 4;
    const int tx = tid & 15, ty = tid >> 4;
    const float* Ap = A + (long)(m0 + lr) * K + lc;
    const float* Bp = B + (long)(n0 + lr) * K + lc;
    unsigned long long acc2[8][4];
    #pragma unroll
    for (int i = 0; i < 8; i++)
        #pragma unroll
        for (int j = 0; j < 4; j++) acc2[i][j] = 0ULL;

    float4 av = *(const float4*)Ap;
    float4 bv = *(const float4*)Bp;
    for (int k0 = 0; k0 < K; k0 += 8) {
        __syncthreads();
        As[lc+0][lr]=av.x; As[lc+1][lr]=av.y; As[lc+2][lr]=av.z; As[lc+3][lr]=av.w;
        Bs[lc+0][lr]=bv.x; Bs[lc+1][lr]=bv.y; Bs[lc+2][lr]=bv.z; Bs[lc+3][lr]=bv.w;
        __syncthreads();
        if (k0 + 8 < K) {
            av = *(const float4*)(Ap + k0 + 8);
            bv = *(const float4*)(Bp + k0 + 8);
        }
        #pragma unroll
        for (int kk = 0; kk < 8; kk++) {
            float a[8];
            *(float4*)&a[0] = *(const float4*)&As[kk][ty*8];
            *(float4*)&a[4] = *(const float4*)&As[kk][ty*8+4];
            F4U b0, b1;
            b0.f = *(const float4*)&Bs[kk][tx*8];
            b1.f = *(const float4*)&Bs[kk][tx*8+4];
            unsigned long long bp0 = b0.u[0], bp1 = b0.u[1];
            unsigned long long bp2 = b1.u[0], bp3 = b1.u[1];
            #pragma unroll
            for (int i = 0; i < 8; i++) {
                unsigned long long ad = dup_x2(a[i]);
                fma_x2(acc2[i][0], ad, bp0);
                fma_x2(acc2[i][1], ad, bp1);
                fma_x2(acc2[i][2], ad, bp2);
                fma_x2(acc2[i][3], ad, bp3);
            }
        }
    }
    float bvr[8];
    #pragma unroll
    for (int j = 0; j < 8; j++) bvr[j] = bias[n0 + tx*8 + j];
    #pragma unroll
    for (int i = 0; i < 8; i++) {
        float c[8];
        #pragma unroll
        for (int j = 0; j < 4; j++) unpack_x2(acc2[i][j], c[2*j], c[2*j+1]);
        float* crow = C + (long)(m0 + ty*8 + i) * N + n0 + tx*8;
        *(float4*)crow =
            make_float4(c[0]+bvr[0], c[1]+bvr[1], c[2]+bvr[2], c[3]+bvr[3]);
        *(float4*)(crow + 4) =
            make_float4(c[4]+bvr[4], c[5]+bvr[5], c[6]+bvr[6], c[7]+bvr[7]);
    }
}

// ---------------------------------------------------------------------------
// Context batched GEMM (TN): C[b](F=512,N=512) = sum_l P[l,f] * R[l,h]
// ---------------------------------------------------------------------------
__global__ __launch_bounds__(256) void gemm_tn_ctx_kernel(
    const float* __restrict__ P, const float* __restrict__ R,
    float* __restrict__ C)
{
    __shared__ __align__(16) float As[8][128];
    __shared__ __align__(16) float Bs[8][128];
    const int b  = blockIdx.z;
    const int m0 = blockIdx.x * 128, n0 = blockIdx.y * 128;
    const int tid = threadIdx.x;
    const int lrow = tid >> 5;            // 0..7
    const int c4   = (tid & 31) * 4;      // 0..124
    const int tx = tid & 15, ty = tid >> 4;
    unsigned long long acc2[8][4];
    #pragma unroll
    for (int i = 0; i < 8; i++)
        #pragma unroll
        for (int j = 0; j < 4; j++) acc2[i][j] = 0ULL;

    long base0 = ((long)lrow * 32 + b) * H2;
    float4 av = *(const float4*)(P + base0 + m0 + c4);
    float4 bv = *(const float4*)(R + base0 + n0 + c4);
    for (int l0 = 0; l0 < LSEQ; l0 += 8) {
        __syncthreads();
        *(float4*)&As[lrow][c4] = av;
        *(float4*)&Bs[lrow][c4] = bv;
        __syncthreads();
        if (l0 + 8 < LSEQ) {
            long base = ((long)(l0 + 8 + lrow) * 32 + b) * H2;
            av = *(const float4*)(P + base + m0 + c4);
            bv = *(const float4*)(R + base + n0 + c4);
        }
        #pragma unroll
        for (int kk = 0; kk < 8; kk++) {
            float a[8];
            *(float4*)&a[0] = *(const float4*)&As[kk][ty*8];
            *(float4*)&a[4] = *(const float4*)&As[kk][ty*8+4];
            F4U b0, b1;
            b0.f = *(const float4*)&Bs[kk][tx*8];
            b1.f = *(const float4*)&Bs[kk][tx*8+4];
            unsigned long long bp0 = b0.u[0], bp1 = b0.u[1];
            unsigned long long bp2 = b1.u[0], bp3 = b1.u[1];
            #pragma unroll
            for (int i = 0; i < 8; i++) {
                unsigned long long ad = dup_x2(a[i]);
                fma_x2(acc2[i][0], ad, bp0);
                fma_x2(acc2[i][1], ad, bp1);
                fma_x2(acc2[i][2], ad, bp2);
                fma_x2(acc2[i][3], ad, bp3);
            }
        }
    }
    #pragma unroll
    for (int i = 0; i < 8; i++) {
        float c[8];
        #pragma unroll
        for (int j = 0; j < 4; j++) unpack_x2(acc2[i][j], c[2*j], c[2*j+1]);
        float* crow = C + ((long)b * NF + m0 + ty*8 + i) * H2 + n0 + tx*8;
        *(float4*)crow       = make_float4(c[0], c[1], c[2], c[3]);
        *(float4*)(crow + 4) = make_float4(c[4], c[5], c[6], c[7]);
    }
}

// ---------------------------------------------------------------------------
// GRU recurrence v4. Persistent, single-poller counter barrier:
//   writers: __stcg h -> L2; __syncthreads; tid0: __threadfence + RED(counter[t])
//   readers: tid0 polls counter[t-1]==64 (one address/step, 256B step stride);
//            no reader fence; h via __ldcg.
// Block (dir, g) owns h-units c0=4g..4g+3 (12 gate rows in SMEM, f32x2 FMA).
// 256 threads = 32 batches x 8 k-splits(32 each).
// ---------------------------------------------------------------------------
__global__ __launch_bounds__(256) void gru_layer_kernel(
    const float* __restrict__ gi,    // (2, 16384, 768)  includes b_ih
    const float* __restrict__ whh,   // (2, 768, 256)
    const float* __restrict__ bhh,   // (2, 768)
    const float* __restrict__ h0,    // (2, 32, 256)
    float* __restrict__ out,         // (16384, 512), dir d writes cols d*256..
    int* __restrict__ cnts)          // (2, LSEQ*CNT_STRIDE)
{
    const int dir = blockIdx.x >> 6;
    const int g   = blockIdx.x & 63;
    const int c0  = g * 4;
    const int tid = threadIdx.x;
    const int b   = tid >> 3;          // 0..31  (batch)
    const int sub = tid & 7;           // 0..7   (k-split)
    const int kbase = sub * 32;

    __shared__ __align__(16) float w_s[12 * 288];   // [row][sub][36]  (pad 4)
    __shared__ float bhh_s[12];

    const float* whh_d = whh + (long)dir * G3 * HID;
    for (int i = tid; i < 12 * 256; i += 256) {
        int row = i >> 8, k = i & 255;
        int R = (row >> 2) * 256 + c0 + (row & 3);   // gate*256 + c0 + j
        w_s[row * 288 + (k >> 5) * 36 + (k & 31)] = whh_d[(long)R * HID + k];
    }
    if (tid < 12)
        bhh_s[tid] = bhh[dir * G3 + (tid >> 2) * 256 + c0 + (tid & 3)];
    __syncthreads();

    const float* gi_d = gi + (long)dir * LB * G3;
    int* cnt = cnts + dir * (LSEQ * CNT_STRIDE);
    const int srcsub = g >> 3;   // lane (within 8-group) holding h_prev[c0..c0+3]
    const int qh     = g & 7;    // float4 index within that lane's h[]

    for (int t = 0; t < LSEQ; t++) {
        int p  = dir ? (LSEQ - 1 - t) : t;
        int pp = dir ? (p + 1) : (p - 1);

        // prefetch gi for this step (independent of the barrier)
        float4 ga, gz, gn;
        if (sub == 0) {
            const float* grow = gi_d + ((long)p * BSZ + b) * G3;
            ga = __ldg((const float4*)(grow + c0));
            gz = __ldg((const float4*)(grow + 256 + c0));
            gn = __ldg((const float4*)(grow + 512 + c0));
        }

        // barrier: wait for all 64 blocks of this dir to finish step t-1
        if (t > 0) {
            if (tid == 0) {
                volatile int* c = (volatile int*)(cnt + (t - 1) * CNT_STRIDE);
                while (*c < GRU_G) { }
            }
            __syncthreads();
        }

        // load h_prev slice (batch b, k = kbase..kbase+31) from L2
        F4U h[8];
        const float* hb = (t == 0)
            ? (h0 + ((long)dir * BSZ + b) * HID)
            : (out + ((long)pp * BSZ + b) * H2 + dir * HID);
        #pragma unroll
        for (int q = 0; q < 8; q++)
            h[q].f = __ldcg((const float4*)(hb + kbase + q * 4));

        // packed-pair FMA: acc2[row] accumulates (even,odd) partial sums
        unsigned long long acc2[12];
        #pragma unroll
        for (int r = 0; r < 12; r++) acc2[r] = 0ULL;
        #pragma unroll
        for (int q = 0; q < 8; q++) {
            #pragma unroll
            for (int row = 0; row < 12; row++) {
                F4U w;
                w.f = *(const float4*)&w_s[row * 288 + sub * 36 + q * 4];
                fma_x2(acc2[row], h[q].u[0], w.u[0]);
                fma_x2(acc2[row], h[q].u[1], w.u[1]);
            }
        }

        // hp = h_prev[b, c0..c0+3] via intra-group 64-bit shuffles
        unsigned long long hp01 = __shfl_sync(0xffffffffu, h[qh].u[0], srcsub, 8);
        unsigned long long hp23 = __shfl_sync(0xffffffffu, h[qh].u[1], srcsub, 8);

        // collapse pairs to scalars, then reduce over the 8 k-split lanes
        float accs[12];
        #pragma unroll
        for (int r = 0; r < 12; r++) {
            float lo, hi; unpack_x2(acc2[r], lo, hi);
            accs[r] = lo + hi;
        }
        #pragma unroll
        for (int off = 4; off; off >>= 1)
            #pragma unroll
            for (int r = 0; r < 12; r++)
                accs[r] += __shfl_down_sync(0xffffffffu, accs[r], off, 8);

        if (sub == 0) {
            float hp[4];
            unpack_x2(hp01, hp[0], hp[1]);
            unpack_x2(hp23, hp[2], hp[3]);
            float gav[4], gzv[4], gnv[4], hn[4];
            *(float4*)gav = ga; *(float4*)gzv = gz; *(float4*)gnv = gn;
            #pragma unroll
            for (int j = 0; j < 4; j++) {
                float r = fast_sig(gav[j] + bhh_s[j]     + accs[j]);
                float z = fast_sig(gzv[j] + bhh_s[4 + j] + accs[4 + j]);
                float n = fast_tanh(gnv[j] + r * (accs[8 + j] + bhh_s[8 + j]));
                hn[j] = (1.f - z) * n + z * hp[j];
            }
            // straight to L2 (coherence point)
            __stcg((float4*)(out + ((long)p * BSZ + b) * H2 + dir * HID + c0),
                   make_float4(hn[0], hn[1], hn[2], hn[3]));
        }
        __syncthreads();                 // all writers' stcg issued
        if (tid == 0) {
            __threadfence();             // single-thread gpu-scope fence
            atomicAdd(cnt + t * CNT_STRIDE, 1);   // result unused -> REDG
        }
    }
}

// ---------------------------------------------------------------------------
// Row softmax over 512 features, in place (energies -> probs)
// ---------------------------------------------------------------------------
__global__ void softmax_kernel(float* __restrict__ E) {
    int row = blockIdx.x, tid = threadIdx.x;   // 128 threads
    float* Er = E + (long)row * NF;
    float4 v = ((float4*)Er)[tid];
    __shared__ float sred[8];
    float m = fmaxf(fmaxf(v.x, v.y), fmaxf(v.z, v.w));
    #pragma unroll
    for (int off = 16; off; off >>= 1) m = fmaxf(m, __shfl_xor_sync(0xffffffffu, m, off));
    if ((tid & 31) == 0) sred[tid >> 5] = m;
    __syncthreads();
    m = fmaxf(fmaxf(sred[0], sred[1]), fmaxf(sred[2], sred[3]));
    float e0 = expf(v.x - m), e1 = expf(v.y - m), e2 = expf(v.z - m), e3 = expf(v.w - m);
    float s = e0 + e1 + e2 + e3;
    #pragma unroll
    for (int off = 16; off; off >>= 1) s += __shfl_xor_sync(0xffffffffu, s, off);
    __syncthreads();
    if ((tid & 31) == 0) sred[4 + (tid >> 5)] = s;
    __syncthreads();
    s = sred[4] + sred[5] + sred[6] + sred[7];
    float inv = 1.f / s;
    ((float4*)Er)[tid] = make_float4(e0 * inv, e1 * inv, e2 * inv, e3 * inv);
}

// attn_out[b][f][l] = probs[(l*32+b)*512 + f]   (tiled transpose)
__global__ void transpose_kernel(const float* __restrict__ P, float* __restrict__ outp) {
    __shared__ float t[32][33];
    int b = blockIdx.z;
    int f0 = blockIdx.x * 32, l0 = blockIdx.y * 32;
    int tx = threadIdx.x, ty = threadIdx.y;   // (32,8)
    #pragma unroll
    for (int i = 0; i < 32; i += 8)
        t[ty + i][tx] = P[((long)(l0 + ty + i) * BSZ + b) * NF + f0 + tx];
    __syncthreads();
    #pragma unroll
    for (int i = 0; i < 32; i += 8)
        outp[((long)b * NF + f0 + ty + i) * LSEQ + l0 + tx] = t[tx][ty + i];
}

// ---------------------------------------------------------------------------
// Launch
// ---------------------------------------------------------------------------
template <typename T>
static T* symaddr(const void* sym) {
    void* p = nullptr;
    cudaGetSymbolAddress(&p, sym);
    return (T*)p;
}

extern "C" void kernel_launch(void* const* d_in, const int* in_sizes, int n_in,
                              void* d_out, int out_size) {
    const int*   tok    = (const int*)d_in[0];
    const float* hidden = (const float*)d_in[2];
    const float* fe     = (const float*)d_in[3];
    const float* emb    = (const float*)d_in[4];
    const float* w_ih0  = (const float*)d_in[5];
    const float* w_hh0  = (const float*)d_in[6];
    const float* b_ih0  = (const float*)d_in[7];
    const float* b_hh0  = (const float*)d_in[8];
    const float* w_ih1  = (const float*)d_in[9];
    const float* w_hh1  = (const float*)d_in[10];
    const float* b_ih1  = (const float*)d_in[11];
    const float* b_hh1  = (const float*)d_in[12];
    const float* la_w   = (const float*)d_in[13];
    const float* la_b   = (const float*)d_in[14];
    const float* fa_w   = (const float*)d_in[15];
    const float* fa_b   = (const float*)d_in[16];
    const float* vmat   = (const float*)d_in[17];

    float* ctx_out  = (float*)d_out;                       // (32,512,512)
    float* attn_out = ctx_out + (size_t)BSZ * NF * LSEQ;   // (32,512,512)

    float* x   = symaddr<float>(d_x);
    float* gi  = symaddr<float>(d_gi);
    float* s0  = symaddr<float>(d_seq0);
    float* s1  = symaddr<float>(d_seq1);
    float* en  = symaddr<float>(d_energy);
    float* Mb  = symaddr<float>(d_Mb);
    float* cb  = symaddr<float>(d_cb);
    int*   flg = symaddr<int>(d_flags);

    zero_flags_kernel<<<(2 * 2 * LSEQ * CNT_STRIDE + 255) / 256, 256>>>(flg);
    embed_kernel<<<LB, 64>>>(tok, emb, x);
    build_M_kernel<<<NF, 128>>>(fe, vmat, fa_w, la_w, fa_b, la_b, Mb, cb);

    dim3 gGi(LB / 128, G3 / 128);   // (128, 6)
    gemm_nt_kernel<<<gGi, 256>>>(x, w_ih0,            b_ih0,       gi,                16384, 768, 256);
    gemm_nt_kernel<<<gGi, 256>>>(x, w_ih0 + 768*256,  b_ih0 + 768, gi + (long)LB*G3,  16384, 768, 256);

    gru_layer_kernel<<<128, 256>>>(gi, w_hh0, b_hh0, hidden, s0, flg);

    gemm_nt_kernel<<<gGi, 256>>>(s0, w_ih1,           b_ih1,       gi,                16384, 768, 512);
    gemm_nt_kernel<<<gGi, 256>>>(s0, w_ih1 + 768*512, b_ih1 + 768, gi + (long)LB*G3,  16384, 768, 512);

    gru_layer_kernel<<<128, 256>>>(gi, w_hh1, b_hh1, hidden + 2*BSZ*HID, s1,
                                   flg + 2 * LSEQ * CNT_STRIDE);

    dim3 gEn(LB / 128, NF / 128);   // (128, 4)
    gemm_nt_kernel<<<gEn, 256>>>(s1, Mb, cb, en, 16384, 512, 512);

    softmax_kernel<<<LB, 128>>>(en);

    dim3 gT(NF / 32, LSEQ / 32, BSZ);
    transpose_kernel<<<gT, dim3(32, 8)>>>(en, attn_out);

    dim3 gC(NF / 128, H2 / 128, BSZ);   // (4,4,32)
    gemm_tn_ctx_kernel<<<gC, 256>>>(en, s1, ctx_out);
}

// round 5
// speedup vs baseline: 1.3387x; 1.0176x over previous
#include <cuda_runtime.h>
#include <math.h>

// ---------------------------------------------------------------------------
// Problem constants
// ---------------------------------------------------------------------------
#define LSEQ 512
#define BSZ  32
#define HID  256
#define LB   (LSEQ*BSZ)   // 16384 rows (row index = l*32 + b)
#define G3   768          // 3*H
#define H2   512          // 2*H
#define NF   512          // attention feature rows (384 fe + 128 v)
#define GRU_G 64          // blocks per direction in recurrence
#define FLG_STRIDE 64     // ints between per-block flags (256B -> distinct lines/slices)

// ---------------------------------------------------------------------------
// Scratch (device globals; no allocation allowed)
// ---------------------------------------------------------------------------
__device__ float d_x[LB * 256];            // embedded input (L,B,E)
__device__ float d_gi[2 * LB * G3];        // input-projection gates, reused l0/l1
__device__ float d_seq0[LB * H2];          // layer0 output (L,B,2H)
__device__ float d_seq1[LB * H2];          // layer1 output = rnn (L,B,2H)
__device__ float d_energy[LB * NF];        // energies -> probs (in place)
__device__ float d_Mb[NF * H2];            // fused attention matrix (F,2H)
__device__ float d_cb[NF];                 // fused attention bias
__device__ int   d_flags[2 * 2 * GRU_G * FLG_STRIDE];  // layer x dir x block flags

// ---------------------------------------------------------------------------
// helpers
// ---------------------------------------------------------------------------
__device__ __forceinline__ float fast_sig(float x) { return 1.0f / (1.0f + __expf(-x)); }
__device__ __forceinline__ float fast_tanh(float x) { return 2.0f / (1.0f + __expf(-2.0f * x)) - 1.0f; }

union F4U { float4 f; float fa[4]; unsigned long long u[2]; };

__device__ __forceinline__ void fma_x2(unsigned long long& d,
                                       unsigned long long a,
                                       unsigned long long b) {
    asm("fma.rn.f32x2 %0, %1, %2, %0;" : "+l"(d) : "l"(a), "l"(b));
}
__device__ __forceinline__ unsigned long long dup_x2(float v) {
    unsigned long long r; unsigned u = __float_as_uint(v);
    asm("mov.b64 %0, {%1, %1};" : "=l"(r) : "r"(u));
    return r;
}
__device__ __forceinline__ void unpack_x2(unsigned long long p, float& lo, float& hi) {
    unsigned a, b;
    asm("mov.b64 {%0, %1}, %2;" : "=r"(a), "=r"(b) : "l"(p));
    lo = __uint_as_float(a); hi = __uint_as_float(b);
}

__global__ void zero_flags_kernel(int* flags) {
    int i = blockIdx.x * 256 + threadIdx.x;
    if (i < 2 * 2 * GRU_G * FLG_STRIDE) flags[i] = 0;
}

// x[(l*32+b)*256 + :] = emb[tok[b*512+l]]
__global__ void embed_kernel(const int* __restrict__ tok,
                             const float* __restrict__ emb,
                             float* __restrict__ X) {
    int r = blockIdx.x;                 // 0..16383
    int l = r >> 5, b = r & 31;
    int t = tok[b * LSEQ + l];
    const float4* src = (const float4*)(emb + (long)t * 256);
    float4* dst = (float4*)(X + (long)r * 256);
    dst[threadIdx.x] = src[threadIdx.x];   // 64 threads * float4
}

// Fold attention projections into Mb (F,2H) and cb (F)
__global__ void build_M_kernel(const float* __restrict__ fe,
                               const float* __restrict__ vmat,
                               const float* __restrict__ fa_w,
                               const float* __restrict__ la_w,
                               const float* __restrict__ fa_b,
                               const float* __restrict__ la_b,
                               float* __restrict__ Mb, float* __restrict__ cb) {
    int f = blockIdx.x;                 // 0..511
    int tid = threadIdx.x;              // 128
    __shared__ float u[256];
    __shared__ float red[128];
    const float* U  = (f < 384) ? (fe + (long)f * 256) : (vmat + (long)(f - 384) * 256);
    const float* W  = (f < 384) ? fa_w : la_w;
    const float* Bv = (f < 384) ? fa_b : la_b;
    u[tid]       = U[tid];
    u[tid + 128] = U[tid + 128];
    float cpart = u[tid] * Bv[tid] + u[tid + 128] * Bv[tid + 128];
    __syncthreads();
    float a0 = 0.f, a1 = 0.f, a2 = 0.f, a3 = 0.f;
    #pragma unroll 4
    for (int d = 0; d < 256; d++) {
        float ud = u[d];
        float4 w = *(const float4*)(W + (long)d * H2 + tid * 4);
        a0 += ud * w.x; a1 += ud * w.y; a2 += ud * w.z; a3 += ud * w.w;
    }
    *(float4*)(Mb + (long)f * H2 + tid * 4) = make_float4(a0, a1, a2, a3);
    red[tid] = cpart; __syncthreads();
    for (int s = 64; s; s >>= 1) { if (tid < s) red[tid] += red[tid + s]; __syncthreads(); }
    if (tid == 0) cb[f] = red[0];
}

// ---------------------------------------------------------------------------
// C(M,N) = A(M,K) @ B(N,K)^T + bias(N).   128x128 tile, BK=8, 256 thr,
// 8x8 micro-tile via packed fma.rn.f32x2 (acc pairs along N).
// ---------------------------------------------------------------------------
__global__ __launch_bounds__(256) void gemm_nt_kernel(
    const float* __restrict__ A, const float* __restrict__ B,
    const float* __restrict__ bias, float* __restrict__ C,
    int M, int N, int K)
{
    __shared__ __align__(16) float As[8][128];
    __shared__ __align__(16) float Bs[8][128];
    const int m0 = blockIdx.x * 128, n0 = blockIdx.y * 128;
    const int tid = threadIdx.x;
    const int lr = tid >> 1, lc = (tid & 1) * 4;
    const int tx = tid & 15, ty = tid >> 4;
    const float* Ap = A + (long)(m0 + lr) * K + lc;
    const float* Bp = B + (long)(n0 + lr) * K + lc;
    unsigned long long acc2[8][4];
    #pragma unroll
    for (int i = 0; i < 8; i++)
        #pragma unroll
        for (int j = 0; j < 4; j++) acc2[i][j] = 0ULL;

    float4 av = *(const float4*)Ap;
    float4 bv = *(const float4*)Bp;
    for (int k0 = 0; k0 < K; k0 += 8) {
        __syncthreads();
        As[lc+0][lr]=av.x; As[lc+1][lr]=av.y; As[lc+2][lr]=av.z; As[lc+3][lr]=av.w;
        Bs[lc+0][lr]=bv.x; Bs[lc+1][lr]=bv.y; Bs[lc+2][lr]=bv.z; Bs[lc+3][lr]=bv.w;
        __syncthreads();
        if (k0 + 8 < K) {
            av = *(const float4*)(Ap + k0 + 8);
            bv = *(const float4*)(Bp + k0 + 8);
        }
        #pragma unroll
        for (int kk = 0; kk < 8; kk++) {
            float a[8];
            *(float4*)&a[0] = *(const float4*)&As[kk][ty*8];
            *(float4*)&a[4] = *(const float4*)&As[kk][ty*8+4];
            F4U b0, b1;
            b0.f = *(const float4*)&Bs[kk][tx*8];
            b1.f = *(const float4*)&Bs[kk][tx*8+4];
            unsigned long long bp0 = b0.u[0], bp1 = b0.u[1];
            unsigned long long bp2 = b1.u[0], bp3 = b1.u[1];
            #pragma unroll
            for (int i = 0; i < 8; i++) {
                unsigned long long ad = dup_x2(a[i]);
                fma_x2(acc2[i][0], ad, bp0);
                fma_x2(acc2[i][1], ad, bp1);
                fma_x2(acc2[i][2], ad, bp2);
                fma_x2(acc2[i][3], ad, bp3);
            }
        }
    }
    float bvr[8];
    #pragma unroll
    for (int j = 0; j < 8; j++) bvr[j] = bias[n0 + tx*8 + j];
    #pragma unroll
    for (int i = 0; i < 8; i++) {
        float c[8];
        #pragma unroll
        for (int j = 0; j < 4; j++) unpack_x2(acc2[i][j], c[2*j], c[2*j+1]);
        float* crow = C + (long)(m0 + ty*8 + i) * N + n0 + tx*8;
        *(float4*)crow =
            make_float4(c[0]+bvr[0], c[1]+bvr[1], c[2]+bvr[2], c[3]+bvr[3]);
        *(float4*)(crow + 4) =
            make_float4(c[4]+bvr[4], c[5]+bvr[5], c[6]+bvr[6], c[7]+bvr[7]);
    }
}

// ---------------------------------------------------------------------------
// Context batched GEMM (TN): C[b](F=512,N=512) = sum_l P[l,f] * R[l,h]
// ---------------------------------------------------------------------------
__global__ __launch_bounds__(256) void gemm_tn_ctx_kernel(
    const float* __restrict__ P, const float* __restrict__ R,
    float* __restrict__ C)
{
    __shared__ __align__(16) float As[8][128];
    __shared__ __align__(16) float Bs[8][128];
    const int b  = blockIdx.z;
    const int m0 = blockIdx.x * 128, n0 = blockIdx.y * 128;
    const int tid = threadIdx.x;
    const int lrow = tid >> 5;            // 0..7
    const int c4   = (tid & 31) * 4;      // 0..124
    const int tx = tid & 15, ty = tid >> 4;
    unsigned long long acc2[8][4];
    #pragma unroll
    for (int i = 0; i < 8; i++)
        #pragma unroll
        for (int j = 0; j < 4; j++) acc2[i][j] = 0ULL;

    long base0 = ((long)lrow * 32 + b) * H2;
    float4 av = *(const float4*)(P + base0 + m0 + c4);
    float4 bv = *(const float4*)(R + base0 + n0 + c4);
    for (int l0 = 0; l0 < LSEQ; l0 += 8) {
        __syncthreads();
        *(float4*)&As[lrow][c4] = av;
        *(float4*)&Bs[lrow][c4] = bv;
        __syncthreads();
        if (l0 + 8 < LSEQ) {
            long base = ((long)(l0 + 8 + lrow) * 32 + b) * H2;
            av = *(const float4*)(P + base + m0 + c4);
            bv = *(const float4*)(R + base + n0 + c4);
        }
        #pragma unroll
        for (int kk = 0; kk < 8; kk++) {
            float a[8];
            *(float4*)&a[0] = *(const float4*)&As[kk][ty*8];
            *(float4*)&a[4] = *(const float4*)&As[kk][ty*8+4];
            F4U b0, b1;
            b0.f = *(const float4*)&Bs[kk][tx*8];
            b1.f = *(const float4*)&Bs[kk][tx*8+4];
            unsigned long long bp0 = b0.u[0], bp1 = b0.u[1];
            unsigned long long bp2 = b1.u[0], bp3 = b1.u[1];
            #pragma unroll
            for (int i = 0; i < 8; i++) {
                unsigned long long ad = dup_x2(a[i]);
                fma_x2(acc2[i][0], ad, bp0);
                fma_x2(acc2[i][1], ad, bp1);
                fma_x2(acc2[i][2], ad, bp2);
                fma_x2(acc2[i][3], ad, bp3);
            }
        }
    }
    #pragma unroll
    for (int i = 0; i < 8; i++) {
        float c[8];
        #pragma unroll
        for (int j = 0; j < 4; j++) unpack_x2(acc2[i][j], c[2*j], c[2*j+1]);
        float* crow = C + ((long)b * NF + m0 + ty*8 + i) * H2 + n0 + tx*8;
        *(float4*)crow       = make_float4(c[0], c[1], c[2], c[3]);
        *(float4*)(crow + 4) = make_float4(c[4], c[5], c[6], c[7]);
    }
}

// ---------------------------------------------------------------------------
// GRU recurrence v5. Persistent, ATOMIC-FREE slice-spread flag barrier:
//   publish: stcg h; __syncthreads; tid0: __threadfence + volatile store
//            flg[g*FLG_STRIDE] = t+1   (own line -> no RMW serialization)
//   wait:    threads 0..63 each spin on a DISTINCT flag line (parallel
//            detection, ~64 pollers per line at ~400cyc period)
// Block (dir, g) owns h-units c0=4g..4g+3 (12 gate rows in SMEM, f32x2 FMA).
// 256 threads = 32 batches x 8 k-splits(32 each).
// ---------------------------------------------------------------------------
__global__ __launch_bounds__(256) void gru_layer_kernel(
    const float* __restrict__ gi,    // (2, 16384, 768)  includes b_ih
    const float* __restrict__ whh,   // (2, 768, 256)
    const float* __restrict__ bhh,   // (2, 768)
    const float* __restrict__ h0,    // (2, 32, 256)
    float* __restrict__ out,         // (16384, 512), dir d writes cols d*256..
    int* __restrict__ flags)         // (2, GRU_G*FLG_STRIDE)
{
    const int dir = blockIdx.x >> 6;
    const int g   = blockIdx.x & 63;
    const int c0  = g * 4;
    const int tid = threadIdx.x;
    const int b   = tid >> 3;          // 0..31  (batch)
    const int sub = tid & 7;           // 0..7   (k-split)
    const int kbase = sub * 32;

    __shared__ __align__(16) float w_s[12 * 288];   // [row][sub][36]  (pad 4)
    __shared__ float bhh_s[12];

    const float* whh_d = whh + (long)dir * G3 * HID;
    for (int i = tid; i < 12 * 256; i += 256) {
        int row = i >> 8, k = i & 255;
        int R = (row >> 2) * 256 + c0 + (row & 3);   // gate*256 + c0 + j
        w_s[row * 288 + (k >> 5) * 36 + (k & 31)] = whh_d[(long)R * HID + k];
    }
    if (tid < 12)
        bhh_s[tid] = bhh[dir * G3 + (tid >> 2) * 256 + c0 + (tid & 3)];
    __syncthreads();

    const float* gi_d = gi + (long)dir * LB * G3;
    volatile int* flg = (volatile int*)(flags + dir * (GRU_G * FLG_STRIDE));
    const int srcsub = g >> 3;   // lane (within 8-group) holding h_prev[c0..c0+3]
    const int qh     = g & 7;    // float4 index within that lane's h[]

    for (int t = 0; t < LSEQ; t++) {
        int p  = dir ? (LSEQ - 1 - t) : t;
        int pp = dir ? (p + 1) : (p - 1);

        // prefetch gi for this step (independent of the barrier)
        float4 ga, gz, gn;
        if (sub == 0) {
            const float* grow = gi_d + ((long)p * BSZ + b) * G3;
            ga = __ldg((const float4*)(grow + c0));
            gz = __ldg((const float4*)(grow + 256 + c0));
            gn = __ldg((const float4*)(grow + 512 + c0));
        }

        // barrier: wait for all 64 blocks of this dir to finish step t-1.
        // 64 pollers, each spinning on its own flag line -> parallel detect.
        if (t > 0) {
            if (tid < GRU_G) {
                volatile int* f = flg + tid * FLG_STRIDE;
                while (*f < t) { }
            }
            __syncthreads();
        }

        // load h_prev slice (batch b, k = kbase..kbase+31) from L2
        F4U h[8];
        const float* hb = (t == 0)
            ? (h0 + ((long)dir * BSZ + b) * HID)
            : (out + ((long)pp * BSZ + b) * H2 + dir * HID);
        #pragma unroll
        for (int q = 0; q < 8; q++)
            h[q].f = __ldcg((const float4*)(hb + kbase + q * 4));

        // packed-pair FMA: acc2[row] accumulates (even,odd) partial sums
        unsigned long long acc2[12];
        #pragma unroll
        for (int r = 0; r < 12; r++) acc2[r] = 0ULL;
        #pragma unroll
        for (int q = 0; q < 8; q++) {
            #pragma unroll
            for (int row = 0; row < 12; row++) {
                F4U w;
                w.f = *(const float4*)&w_s[row * 288 + sub * 36 + q * 4];
                fma_x2(acc2[row], h[q].u[0], w.u[0]);
                fma_x2(acc2[row], h[q].u[1], w.u[1]);
            }
        }

        // hp = h_prev[b, c0..c0+3] via intra-group 64-bit shuffles
        unsigned long long hp01 = __shfl_sync(0xffffffffu, h[qh].u[0], srcsub, 8);
        unsigned long long hp23 = __shfl_sync(0xffffffffu, h[qh].u[1], srcsub, 8);

        // collapse pairs to scalars, then reduce over the 8 k-split lanes
        float accs[12];
        #pragma unroll
        for (int r = 0; r < 12; r++) {
            float lo, hi; unpack_x2(acc2[r], lo, hi);
            accs[r] = lo + hi;
        }
        #pragma unroll
        for (int off = 4; off; off >>= 1)
            #pragma unroll
            for (int r = 0; r < 12; r++)
                accs[r] += __shfl_down_sync(0xffffffffu, accs[r], off, 8);

        if (sub == 0) {
            float hp[4];
            unpack_x2(hp01, hp[0], hp[1]);
            unpack_x2(hp23, hp[2], hp[3]);
            float gav[4], gzv[4], gnv[4], hn[4];
            *(float4*)gav = ga; *(float4*)gzv = gz; *(float4*)gnv = gn;
            #pragma unroll
            for (int j = 0; j < 4; j++) {
                float r = fast_sig(gav[j] + bhh_s[j]     + accs[j]);
                float z = fast_sig(gzv[j] + bhh_s[4 + j] + accs[4 + j]);
                float n = fast_tanh(gnv[j] + r * (accs[8 + j] + bhh_s[8 + j]));
                hn[j] = (1.f - z) * n + z * hp[j];
            }
            // straight to L2 (coherence point)
            __stcg((float4*)(out + ((long)p * BSZ + b) * H2 + dir * HID + c0),
                   make_float4(hn[0], hn[1], hn[2], hn[3]));
        }
        __syncthreads();                 // all writers' stcg issued
        if (tid == 0) {
            __threadfence();             // single-thread gpu-scope fence
            flg[g * FLG_STRIDE] = t + 1; // plain store, own line (no RMW)
        }
    }
}

// ---------------------------------------------------------------------------
// Row softmax over 512 features, in place (energies -> probs)
// ---------------------------------------------------------------------------
__global__ void softmax_kernel(float* __restrict__ E) {
    int row = blockIdx.x, tid = threadIdx.x;   // 128 threads
    float* Er = E + (long)row * NF;
    float4 v = ((float4*)Er)[tid];
    __shared__ float sred[8];
    float m = fmaxf(fmaxf(v.x, v.y), fmaxf(v.z, v.w));
    #pragma unroll
    for (int off = 16; off; off >>= 1) m = fmaxf(m, __shfl_xor_sync(0xffffffffu, m, off));
    if ((tid & 31) == 0) sred[tid >> 5] = m;
    __syncthreads();
    m = fmaxf(fmaxf(sred[0], sred[1]), fmaxf(sred[2], sred[3]));
    float e0 = expf(v.x - m), e1 = expf(v.y - m), e2 = expf(v.z - m), e3 = expf(v.w - m);
    float s = e0 + e1 + e2 + e3;
    #pragma unroll
    for (int off = 16; off; off >>= 1) s += __shfl_xor_sync(0xffffffffu, s, off);
    __syncthreads();
    if ((tid & 31) == 0) sred[4 + (tid >> 5)] = s;
    __syncthreads();
    s = sred[4] + sred[5] + sred[6] + sred[7];
    float inv = 1.f / s;
    ((float4*)Er)[tid] = make_float4(e0 * inv, e1 * inv, e2 * inv, e3 * inv);
}

// attn_out[b][f][l] = probs[(l*32+b)*512 + f]   (tiled transpose)
__global__ void transpose_kernel(const float* __restrict__ P, float* __restrict__ outp) {
    __shared__ float t[32][33];
    int b = blockIdx.z;
    int f0 = blockIdx.x * 32, l0 = blockIdx.y * 32;
    int tx = threadIdx.x, ty = threadIdx.y;   // (32,8)
    #pragma unroll
    for (int i = 0; i < 32; i += 8)
        t[ty + i][tx] = P[((long)(l0 + ty + i) * BSZ + b) * NF + f0 + tx];
    __syncthreads();
    #pragma unroll
    for (int i = 0; i < 32; i += 8)
        outp[((long)b * NF + f0 + ty + i) * LSEQ + l0 + tx] = t[tx][ty + i];
}

// ---------------------------------------------------------------------------
// Launch
// ---------------------------------------------------------------------------
template <typename T>
static T* symaddr(const void* sym) {
    void* p = nullptr;
    cudaGetSymbolAddress(&p, sym);
    return (T*)p;
}

extern "C" void kernel_launch(void* const* d_in, const int* in_sizes, int n_in,
                              void* d_out, int out_size) {
    const int*   tok    = (const int*)d_in[0];
    const float* hidden = (const float*)d_in[2];
    const float* fe     = (const float*)d_in[3];
    const float* emb    = (const float*)d_in[4];
    const float* w_ih0  = (const float*)d_in[5];
    const float* w_hh0  = (const float*)d_in[6];
    const float* b_ih0  = (const float*)d_in[7];
    const float* b_hh0  = (const float*)d_in[8];
    const float* w_ih1  = (const float*)d_in[9];
    const float* w_hh1  = (const float*)d_in[10];
    const float* b_ih1  = (const float*)d_in[11];
    const float* b_hh1  = (const float*)d_in[12];
    const float* la_w   = (const float*)d_in[13];
    const float* la_b   = (const float*)d_in[14];
    const float* fa_w   = (const float*)d_in[15];
    const float* fa_b   = (const float*)d_in[16];
    const float* vmat   = (const float*)d_in[17];

    float* ctx_out  = (float*)d_out;                       // (32,512,512)
    float* attn_out = ctx_out + (size_t)BSZ * NF * LSEQ;   // (32,512,512)

    float* x   = symaddr<float>(d_x);
    float* gi  = symaddr<float>(d_gi);
    float* s0  = symaddr<float>(d_seq0);
    float* s1  = symaddr<float>(d_seq1);
    float* en  = symaddr<float>(d_energy);
    float* Mb  = symaddr<float>(d_Mb);
    float* cb  = symaddr<float>(d_cb);
    int*   flg = symaddr<int>(d_flags);

    zero_flags_kernel<<<(2 * 2 * GRU_G * FLG_STRIDE + 255) / 256, 256>>>(flg);
    embed_kernel<<<LB, 64>>>(tok, emb, x);
    build_M_kernel<<<NF, 128>>>(fe, vmat, fa_w, la_w, fa_b, la_b, Mb, cb);

    dim3 gGi(LB / 128, G3 / 128);   // (128, 6)
    gemm_nt_kernel<<<gGi, 256>>>(x, w_ih0,            b_ih0,       gi,                16384, 768, 256);
    gemm_nt_kernel<<<gGi, 256>>>(x, w_ih0 + 768*256,  b_ih0 + 768, gi + (long)LB*G3,  16384, 768, 256);

    gru_layer_kernel<<<128, 256>>>(gi, w_hh0, b_hh0, hidden, s0, flg);

    gemm_nt_kernel<<<gGi, 256>>>(s0, w_ih1,           b_ih1,       gi,                16384, 768, 512);
    gemm_nt_kernel<<<gGi, 256>>>(s0, w_ih1 + 768*512, b_ih1 + 768, gi + (long)LB*G3,  16384, 768, 512);

    gru_layer_kernel<<<128, 256>>>(gi, w_hh1, b_hh1, hidden + 2*BSZ*HID, s1,
                                   flg + 2 * GRU_G * FLG_STRIDE);

    dim3 gEn(LB / 128, NF / 128);   // (128, 4)
    gemm_nt_kernel<<<gEn, 256>>>(s1, Mb, cb, en, 16384, 512, 512);

    softmax_kernel<<<LB, 128>>>(en);

    dim3 gT(NF / 32, LSEQ / 32, BSZ);
    transpose_kernel<<<gT, dim3(32, 8)>>>(en, attn_out);

    dim3 gC(NF / 128, H2 / 128, BSZ);   // (4,4,32)
    gemm_tn_ctx_kernel<<<gC, 256>>>(en, s1, ctx_out);
}

// round 6
// speedup vs baseline: 1.3510x; 1.0092x over previous
#include <cuda_runtime.h>
#include <math.h>

// ---------------------------------------------------------------------------
// Problem constants
// ---------------------------------------------------------------------------
#define LSEQ 512
#define BSZ  32
#define HID  256
#define LB   (LSEQ*BSZ)   // 16384 rows (row index = l*32 + b)
#define G3   768          // 3*H
#define H2   512          // 2*H
#define NF   512          // attention feature rows (384 fe + 128 v)
#define GRU_G 64          // blocks per direction in recurrence
#define FLG_STRIDE 64     // ints between per-block flags (256B -> distinct lines/slices)

// ---------------------------------------------------------------------------
// Scratch (device globals; no allocation allowed)
// ---------------------------------------------------------------------------
__device__ float d_x[LB * 256];            // embedded input (L,B,E)
__device__ float d_gi[2 * LB * G3];        // input-projection gates, reused l0/l1
__device__ float d_seq0[LB * H2];          // layer0 output (L,B,2H)
__device__ float d_seq1[LB * H2];          // layer1 output = rnn (L,B,2H)
__device__ float d_energy[LB * NF];        // energies -> probs (in place)
__device__ float d_Mb[NF * H2];            // fused attention matrix (F,2H)
__device__ float d_cb[NF];                 // fused attention bias
__device__ int   d_flags[2 * 2 * GRU_G * FLG_STRIDE];  // layer x dir x block flags

// ---------------------------------------------------------------------------
// helpers
// ---------------------------------------------------------------------------
__device__ __forceinline__ float fast_sig(float x) { return 1.0f / (1.0f + __expf(-x)); }
__device__ __forceinline__ float fast_tanh(float x) { return 2.0f / (1.0f + __expf(-2.0f * x)) - 1.0f; }

union F4U { float4 f; float fa[4]; unsigned long long u[2]; };

__device__ __forceinline__ void fma_x2(unsigned long long& d,
                                       unsigned long long a,
                                       unsigned long long b) {
    asm("fma.rn.f32x2 %0, %1, %2, %0;" : "+l"(d) : "l"(a), "l"(b));
}
__device__ __forceinline__ unsigned long long dup_x2(float v) {
    unsigned long long r; unsigned u = __float_as_uint(v);
    asm("mov.b64 %0, {%1, %1};" : "=l"(r) : "r"(u));
    return r;
}
__device__ __forceinline__ void unpack_x2(unsigned long long p, float& lo, float& hi) {
    unsigned a, b;
    asm("mov.b64 {%0, %1}, %2;" : "=r"(a), "=r"(b) : "l"(p));
    lo = __uint_as_float(a); hi = __uint_as_float(b);
}

__global__ void zero_flags_kernel(int* flags) {
    int i = blockIdx.x * 256 + threadIdx.x;
    if (i < 2 * 2 * GRU_G * FLG_STRIDE) flags[i] = 0;
}

// x[(l*32+b)*256 + :] = emb[tok[b*512+l]]
__global__ void embed_kernel(const int* __restrict__ tok,
                             const float* __restrict__ emb,
                             float* __restrict__ X) {
    int r = blockIdx.x;                 // 0..16383
    int l = r >> 5, b = r & 31;
    int t = tok[b * LSEQ + l];
    const float4* src = (const float4*)(emb + (long)t * 256);
    float4* dst = (float4*)(X + (long)r * 256);
    dst[threadIdx.x] = src[threadIdx.x];   // 64 threads * float4
}

// Fold attention projections into Mb (F,2H) and cb (F)
__global__ void build_M_kernel(const float* __restrict__ fe,
                               const float* __restrict__ vmat,
                               const float* __restrict__ fa_w,
                               const float* __restrict__ la_w,
                               const float* __restrict__ fa_b,
                               const float* __restrict__ la_b,
                               float* __restrict__ Mb, float* __restrict__ cb) {
    int f = blockIdx.x;                 // 0..511
    int tid = threadIdx.x;              // 128
    __shared__ float u[256];
    __shared__ float red[128];
    const float* U  = (f < 384) ? (fe + (long)f * 256) : (vmat + (long)(f - 384) * 256);
    const float* W  = (f < 384) ? fa_w : la_w;
    const float* Bv = (f < 384) ? fa_b : la_b;
    u[tid]       = U[tid];
    u[tid + 128] = U[tid + 128];
    float cpart = u[tid] * Bv[tid] + u[tid + 128] * Bv[tid + 128];
    __syncthreads();
    float a0 = 0.f, a1 = 0.f, a2 = 0.f, a3 = 0.f;
    #pragma unroll 4
    for (int d = 0; d < 256; d++) {
        float ud = u[d];
        float4 w = *(const float4*)(W + (long)d * H2 + tid * 4);
        a0 += ud * w.x; a1 += ud * w.y; a2 += ud * w.z; a3 += ud * w.w;
    }
    *(float4*)(Mb + (long)f * H2 + tid * 4) = make_float4(a0, a1, a2, a3);
    red[tid] = cpart; __syncthreads();
    for (int s = 64; s; s >>= 1) { if (tid < s) red[tid] += red[tid + s]; __syncthreads(); }
    if (tid == 0) cb[f] = red[0];
}

// ---------------------------------------------------------------------------
// C(M,N) = A(M,K) @ B(N,K)^T + bias(N).   128x128 tile, BK=8, 256 thr,
// 8x8 micro-tile via packed fma.rn.f32x2 (acc pairs along N).
// ---------------------------------------------------------------------------
__global__ __launch_bounds__(256) void gemm_nt_kernel(
    const float* __restrict__ A, const float* __restrict__ B,
    const float* __restrict__ bias, float* __restrict__ C,
    int M, int N, int K)
{
    __shared__ __align__(16) float As[8][128];
    __shared__ __align__(16) float Bs[8][128];
    const int m0 = blockIdx.x * 128, n0 = blockIdx.y * 128;
    const int tid = threadIdx.x;
    const int lr = tid >> 1, lc = (tid & 1) * 4;
    const int tx = tid & 15, ty = tid >> 4;
    const float* Ap = A + (long)(m0 + lr) * K + lc;
    const float* Bp = B + (long)(n0 + lr) * K + lc;
    unsigned long long acc2[8][4];
    #pragma unroll
    for (int i = 0; i < 8; i++)
        #pragma unroll
        for (int j = 0; j < 4; j++) acc2[i][j] = 0ULL;

    float4 av = *(const float4*)Ap;
    float4 bv = *(const float4*)Bp;
    for (int k0 = 0; k0 < K; k0 += 8) {
        __syncthreads();
        As[lc+0][lr]=av.x; As[lc+1][lr]=av.y; As[lc+2][lr]=av.z; As[lc+3][lr]=av.w;
        Bs[lc+0][lr]=bv.x; Bs[lc+1][lr]=bv.y; Bs[lc+2][lr]=bv.z; Bs[lc+3][lr]=bv.w;
        __syncthreads();
        if (k0 + 8 < K) {
            av = *(const float4*)(Ap + k0 + 8);
            bv = *(const float4*)(Bp + k0 + 8);
        }
        #pragma unroll
        for (int kk = 0; kk < 8; kk++) {
            float a[8];
            *(float4*)&a[0] = *(const float4*)&As[kk][ty*8];
            *(float4*)&a[4] = *(const float4*)&As[kk][ty*8+4];
            F4U b0, b1;
            b0.f = *(const float4*)&Bs[kk][tx*8];
            b1.f = *(const float4*)&Bs[kk][tx*8+4];
            unsigned long long bp0 = b0.u[0], bp1 = b0.u[1];
            unsigned long long bp2 = b1.u[0], bp3 = b1.u[1];
            #pragma unroll
            for (int i = 0; i < 8; i++) {
                unsigned long long ad = dup_x2(a[i]);
                fma_x2(acc2[i][0], ad, bp0);
                fma_x2(acc2[i][1], ad, bp1);
                fma_x2(acc2[i][2], ad, bp2);
                fma_x2(acc2[i][3], ad, bp3);
            }
        }
    }
    float bvr[8];
    #pragma unroll
    for (int j = 0; j < 8; j++) bvr[j] = bias[n0 + tx*8 + j];
    #pragma unroll
    for (int i = 0; i < 8; i++) {
        float c[8];
        #pragma unroll
        for (int j = 0; j < 4; j++) unpack_x2(acc2[i][j], c[2*j], c[2*j+1]);
        float* crow = C + (long)(m0 + ty*8 + i) * N + n0 + tx*8;
        *(float4*)crow =
            make_float4(c[0]+bvr[0], c[1]+bvr[1], c[2]+bvr[2], c[3]+bvr[3]);
        *(float4*)(crow + 4) =
            make_float4(c[4]+bvr[4], c[5]+bvr[5], c[6]+bvr[6], c[7]+bvr[7]);
    }
}

// ---------------------------------------------------------------------------
// Context batched GEMM (TN): C[b](F=512,N=512) = sum_l P[l,f] * R[l,h]
// ---------------------------------------------------------------------------
__global__ __launch_bounds__(256) void gemm_tn_ctx_kernel(
    const float* __restrict__ P, const float* __restrict__ R,
    float* __restrict__ C)
{
    __shared__ __align__(16) float As[8][128];
    __shared__ __align__(16) float Bs[8][128];
    const int b  = blockIdx.z;
    const int m0 = blockIdx.x * 128, n0 = blockIdx.y * 128;
    const int tid = threadIdx.x;
    const int lrow = tid >> 5;            // 0..7
    const int c4   = (tid & 31) * 4;      // 0..124
    const int tx = tid & 15, ty = tid >> 4;
    unsigned long long acc2[8][4];
    #pragma unroll
    for (int i = 0; i < 8; i++)
        #pragma unroll
        for (int j = 0; j < 4; j++) acc2[i][j] = 0ULL;

    long base0 = ((long)lrow * 32 + b) * H2;
    float4 av = *(const float4*)(P + base0 + m0 + c4);
    float4 bv = *(const float4*)(R + base0 + n0 + c4);
    for (int l0 = 0; l0 < LSEQ; l0 += 8) {
        __syncthreads();
        *(float4*)&As[lrow][c4] = av;
        *(float4*)&Bs[lrow][c4] = bv;
        __syncthreads();
        if (l0 + 8 < LSEQ) {
            long base = ((long)(l0 + 8 + lrow) * 32 + b) * H2;
            av = *(const float4*)(P + base + m0 + c4);
            bv = *(const float4*)(R + base + n0 + c4);
        }
        #pragma unroll
        for (int kk = 0; kk < 8; kk++) {
            float a[8];
            *(float4*)&a[0] = *(const float4*)&As[kk][ty*8];
            *(float4*)&a[4] = *(const float4*)&As[kk][ty*8+4];
            F4U b0, b1;
            b0.f = *(const float4*)&Bs[kk][tx*8];
            b1.f = *(const float4*)&Bs[kk][tx*8+4];
            unsigned long long bp0 = b0.u[0], bp1 = b0.u[1];
            unsigned long long bp2 = b1.u[0], bp3 = b1.u[1];
            #pragma unroll
            for (int i = 0; i < 8; i++) {
                unsigned long long ad = dup_x2(a[i]);
                fma_x2(acc2[i][0], ad, bp0);
                fma_x2(acc2[i][1], ad, bp1);
                fma_x2(acc2[i][2], ad, bp2);
                fma_x2(acc2[i][3], ad, bp3);
            }
        }
    }
    #pragma unroll
    for (int i = 0; i < 8; i++) {
        float c[8];
        #pragma unroll
        for (int j = 0; j < 4; j++) unpack_x2(acc2[i][j], c[2*j], c[2*j+1]);
        float* crow = C + ((long)b * NF + m0 + ty*8 + i) * H2 + n0 + tx*8;
        *(float4*)crow       = make_float4(c[0], c[1], c[2], c[3]);
        *(float4*)(crow + 4) = make_float4(c[4], c[5], c[6], c[7]);
    }
}

// ---------------------------------------------------------------------------
// GRU recurrence v5. Persistent, ATOMIC-FREE slice-spread flag barrier:
//   publish: stcg h; __syncthreads; tid0: __threadfence + volatile store
//            flg[g*FLG_STRIDE] = t+1   (own line -> no RMW serialization)
//   wait:    threads 0..63 each spin on a DISTINCT flag line (parallel
//            detection, ~64 pollers per line at ~400cyc period)
// Block (dir, g) owns h-units c0=4g..4g+3 (12 gate rows in SMEM, f32x2 FMA).
// 256 threads = 32 batches x 8 k-splits(32 each).
// ---------------------------------------------------------------------------
__global__ __launch_bounds__(256) void gru_layer_kernel(
    const float* __restrict__ gi,    // (2, 16384, 768)  includes b_ih
    const float* __restrict__ whh,   // (2, 768, 256)
    const float* __restrict__ bhh,   // (2, 768)
    const float* __restrict__ h0,    // (2, 32, 256)
    float* __restrict__ out,         // (16384, 512), dir d writes cols d*256..
    int* __restrict__ flags)         // (2, GRU_G*FLG_STRIDE)
{
    const int dir = blockIdx.x >> 6;
    const int g   = blockIdx.x & 63;
    const int c0  = g * 4;
    const int tid = threadIdx.x;
    const int b   = tid >> 3;          // 0..31  (batch)
    const int sub = tid & 7;           // 0..7   (k-split)
    const int kbase = sub * 32;

    __shared__ __align__(16) float w_s[12 * 288];   // [row][sub][36]  (pad 4)
    __shared__ float bhh_s[12];

    const float* whh_d = whh + (long)dir * G3 * HID;
    for (int i = tid; i < 12 * 256; i += 256) {
        int row = i >> 8, k = i & 255;
        int R = (row >> 2) * 256 + c0 + (row & 3);   // gate*256 + c0 + j
        w_s[row * 288 + (k >> 5) * 36 + (k & 31)] = whh_d[(long)R * HID + k];
    }
    if (tid < 12)
        bhh_s[tid] = bhh[dir * G3 + (tid >> 2) * 256 + c0 + (tid & 3)];
    __syncthreads();

    const float* gi_d = gi + (long)dir * LB * G3;
    volatile int* flg = (volatile int*)(flags + dir * (GRU_G * FLG_STRIDE));
    const int srcsub = g >> 3;   // lane (within 8-group) holding h_prev[c0..c0+3]
    const int qh     = g & 7;    // float4 index within that lane's h[]

    for (int t = 0; t < LSEQ; t++) {
        int p  = dir ? (LSEQ - 1 - t) : t;
        int pp = dir ? (p + 1) : (p - 1);

        // prefetch gi for this step (independent of the barrier)
        float4 ga, gz, gn;
        if (sub == 0) {
            const float* grow = gi_d + ((long)p * BSZ + b) * G3;
            ga = __ldg((const float4*)(grow + c0));
            gz = __ldg((const float4*)(grow + 256 + c0));
            gn = __ldg((const float4*)(grow + 512 + c0));
        }

        // barrier: wait for all 64 blocks of this dir to finish step t-1.
        // 64 pollers, each spinning on its own flag line -> parallel detect.
        if (t > 0) {
            if (tid < GRU_G) {
                volatile int* f = flg + tid * FLG_STRIDE;
                while (*f < t) { }
            }
            __syncthreads();
        }

        // load h_prev slice (batch b, k = kbase..kbase+31) from L2
        F4U h[8];
        const float* hb = (t == 0)
            ? (h0 + ((long)dir * BSZ + b) * HID)
            : (out + ((long)pp * BSZ + b) * H2 + dir * HID);
        #pragma unroll
        for (int q = 0; q < 8; q++)
            h[q].f = __ldcg((const float4*)(hb + kbase + q * 4));

        // packed-pair FMA: acc2[row] accumulates (even,odd) partial sums
        unsigned long long acc2[12];
        #pragma unroll
        for (int r = 0; r < 12; r++) acc2[r] = 0ULL;
        #pragma unroll
        for (int q = 0; q < 8; q++) {
            #pragma unroll
            for (int row = 0; row < 12; row++) {
                F4U w;
                w.f = *(const float4*)&w_s[row * 288 + sub * 36 + q * 4];
                fma_x2(acc2[row], h[q].u[0], w.u[0]);
                fma_x2(acc2[row], h[q].u[1], w.u[1]);
            }
        }

        // hp = h_prev[b, c0..c0+3] via intra-group 64-bit shuffles
        unsigned long long hp01 = __shfl_sync(0xffffffffu, h[qh].u[0], srcsub, 8);
        unsigned long long hp23 = __shfl_sync(0xffffffffu, h[qh].u[1], srcsub, 8);

        // collapse pairs to scalars, then reduce over the 8 k-split lanes
        float accs[12];
        #pragma unroll
        for (int r = 0; r < 12; r++) {
            float lo, hi; unpack_x2(acc2[r], lo, hi);
            accs[r] = lo + hi;
        }
        #pragma unroll
        for (int off = 4; off; off >>= 1)
            #pragma unroll
            for (int r = 0; r < 12; r++)
                accs[r] += __shfl_down_sync(0xffffffffu, accs[r], off, 8);

        if (sub == 0) {
            float hp[4];
            unpack_x2(hp01, hp[0], hp[1]);
            unpack_x2(hp23, hp[2], hp[3]);
            float gav[4], gzv[4], gnv[4], hn[4];
            *(float4*)gav = ga; *(float4*)gzv = gz; *(float4*)gnv = gn;
            #pragma unroll
            for (int j = 0; j < 4; j++) {
                float r = fast_sig(gav[j] + bhh_s[j]     + accs[j]);
                float z = fast_sig(gzv[j] + bhh_s[4 + j] + accs[4 + j]);
                float n = fast_tanh(gnv[j] + r * (accs[8 + j] + bhh_s[8 + j]));
                hn[j] = (1.f - z) * n + z * hp[j];
            }
            // straight to L2 (coherence point)
            __stcg((float4*)(out + ((long)p * BSZ + b) * H2 + dir * HID + c0),
                   make_float4(hn[0], hn[1], hn[2], hn[3]));
        }
        __syncthreads();                 // all writers' stcg issued
        if (tid == 0) {
            __threadfence();             // single-thread gpu-scope fence
            flg[g * FLG_STRIDE] = t + 1; // plain store, own line (no RMW)
        }
    }
}

// ---------------------------------------------------------------------------
// Row softmax over 512 features, in place (energies -> probs)
// ---------------------------------------------------------------------------
__global__ void softmax_kernel(float* __restrict__ E) {
    int row = blockIdx.x, tid = threadIdx.x;   // 128 threads
    float* Er = E + (long)row * NF;
    float4 v = ((float4*)Er)[tid];
    __shared__ float sred[8];
    float m = fmaxf(fmaxf(v.x, v.y), fmaxf(v.z, v.w));
    #pragma unroll
    for (int off = 16; off; off >>= 1) m = fmaxf(m, __shfl_xor_sync(0xffffffffu, m, off));
    if ((tid & 31) == 0) sred[tid >> 5] = m;
    __syncthreads();
    m = fmaxf(fmaxf(sred[0], sred[1]), fmaxf(sred[2], sred[3]));
    float e0 = expf(v.x - m), e1 = expf(v.y - m), e2 = expf(v.z - m), e3 = expf(v.w - m);
    float s = e0 + e1 + e2 + e3;
    #pragma unroll
    for (int off = 16; off; off >>= 1) s += __shfl_xor_sync(0xffffffffu, s, off);
    __syncthreads();
    if ((tid & 31) == 0) sred[4 + (tid >> 5)] = s;
    __syncthreads();
    s = sred[4] + sred[5] + sred[6] + sred[7];
    float inv = 1.f / s;
    ((float4*)Er)[tid] = make_float4(e0 * inv, e1 * inv, e2 * inv, e3 * inv);
}

// attn_out[b][f][l] = probs[(l*32+b)*512 + f]   (tiled transpose)
__global__ void transpose_kernel(const float* __restrict__ P, float* __restrict__ outp) {
    __shared__ float t[32][33];
    int b = blockIdx.z;
    int f0 = blockIdx.x * 32, l0 = blockIdx.y * 32;
    int tx = threadIdx.x, ty = threadIdx.y;   // (32,8)
    #pragma unroll
    for (int i = 0; i < 32; i += 8)
        t[ty + i][tx] = P[((long)(l0 + ty + i) * BSZ + b) * NF + f0 + tx];
    __syncthreads();
    #pragma unroll
    for (int i = 0; i < 32; i += 8)
        outp[((long)b * NF + f0 + ty + i) * LSEQ + l0 + tx] = t[tx][ty + i];
}

// ---------------------------------------------------------------------------
// Launch
// ---------------------------------------------------------------------------
template <typename T>
static T* symaddr(const void* sym) {
    void* p = nullptr;
    cudaGetSymbolAddress(&p, sym);
    return (T*)p;
}

extern "C" void kernel_launch(void* const* d_in, const int* in_sizes, int n_in,
                              void* d_out, int out_size) {
    const int*   tok    = (const int*)d_in[0];
    const float* hidden = (const float*)d_in[2];
    const float* fe     = (const float*)d_in[3];
    const float* emb    = (const float*)d_in[4];
    const float* w_ih0  = (const float*)d_in[5];
    const float* w_hh0  = (const float*)d_in[6];
    const float* b_ih0  = (const float*)d_in[7];
    const float* b_hh0  = (const float*)d_in[8];
    const float* w_ih1  = (const float*)d_in[9];
    const float* w_hh1  = (const float*)d_in[10];
    const float* b_ih1  = (const float*)d_in[11];
    const float* b_hh1  = (const float*)d_in[12];
    const float* la_w   = (const float*)d_in[13];
    const float* la_b   = (const float*)d_in[14];
    const float* fa_w   = (const float*)d_in[15];
    const float* fa_b   = (const float*)d_in[16];
    const float* vmat   = (const float*)d_in[17];

    float* ctx_out  = (float*)d_out;                       // (32,512,512)
    float* attn_out = ctx_out + (size_t)BSZ * NF * LSEQ;   // (32,512,512)

    float* x   = symaddr<float>(d_x);
    float* gi  = symaddr<float>(d_gi);
    float* s0  = symaddr<float>(d_seq0);
    float* s1  = symaddr<float>(d_seq1);
    float* en  = symaddr<float>(d_energy);
    float* Mb  = symaddr<float>(d_Mb);
    float* cb  = symaddr<float>(d_cb);
    int*   flg = symaddr<int>(d_flags);

    zero_flags_kernel<<<(2 * 2 * GRU_G * FLG_STRIDE + 255) / 256, 256>>>(flg);
    embed_kernel<<<LB, 64>>>(tok, emb, x);
    build_M_kernel<<<NF, 128>>>(fe, vmat, fa_w, la_w, fa_b, la_b, Mb, cb);

    dim3 gGi(LB / 128, G3 / 128);   // (128, 6)
    gemm_nt_kernel<<<gGi, 256>>>(x, w_ih0,            b_ih0,       gi,                16384, 768, 256);
    gemm_nt_kernel<<<gGi, 256>>>(x, w_ih0 + 768*256,  b_ih0 + 768, gi + (long)LB*G3,  16384, 768, 256);

    gru_layer_kernel<<<128, 256>>>(gi, w_hh0, b_hh0, hidden, s0, flg);

    gemm_nt_kernel<<<gGi, 256>>>(s0, w_ih1,           b_ih1,       gi,                16384, 768, 512);
    gemm_nt_kernel<<<gGi, 256>>>(s0, w_ih1 + 768*512, b_ih1 + 768, gi + (long)LB*G3,  16384, 768, 512);

    gru_layer_kernel<<<128, 256>>>(gi, w_hh1, b_hh1, hidden + 2*BSZ*HID, s1,
                                   flg + 2 * GRU_G * FLG_STRIDE);

    dim3 gEn(LB / 128, NF / 128);   // (128, 4)
    gemm_nt_kernel<<<gEn, 256>>>(s1, Mb, cb, en, 16384, 512, 512);

    softmax_kernel<<<LB, 128>>>(en);

    dim3 gT(NF / 32, LSEQ / 32, BSZ);
    transpose_kernel<<<gT, dim3(32, 8)>>>(en, attn_out);

    dim3 gC(NF / 128, H2 / 128, BSZ);   // (4,4,32)
    gemm_tn_ctx_kernel<<<gC, 256>>>(en, s1, ctx_out);
}